// round 5
// baseline (speedup 1.0000x reference)
#include <cuda_runtime.h>
#include <cuda_bf16.h>
#include <stdint.h>
#include <math.h>

// Problem constants
#define BB   4
#define TT   2048
#define CC   1024
#define HH   16
#define DD   64
#define BHTD (BB * HH * TT * DD)

// Scratch (device globals: alloc-free per harness rules)
__device__ float g_qkv[3ull * BHTD];            // [3][B,H,T,D] tf32-valued
__device__ float g_att[(size_t)BB * TT * CC];   // [B,T,C] tf32-valued
__device__ float g_xt[(size_t)BB * TT * CC];    // tf32(x)
__device__ float g_wqkv[3 * CC * CC];           // tf32(qkv_w)
__device__ float g_wproj[CC * CC];              // tf32(proj_w)

// ---------------------------------------------------------------------------
// tf32 / mma / cp.async helpers
// ---------------------------------------------------------------------------
__device__ __forceinline__ uint32_t f2tf(float x) {
    uint32_t u;
    asm("cvt.rna.tf32.f32 %0, %1;" : "=r"(u) : "f"(x));
    return u;
}
__device__ __forceinline__ float f2tff(float x) { return __uint_as_float(f2tf(x)); }

__device__ __forceinline__ void mma8(float* c,
    uint32_t a0, uint32_t a1, uint32_t a2, uint32_t a3,
    uint32_t b0, uint32_t b1)
{
    asm volatile(
        "mma.sync.aligned.m16n8k8.row.col.f32.tf32.tf32.f32 "
        "{%0,%1,%2,%3},{%4,%5,%6,%7},{%8,%9},{%0,%1,%2,%3};"
        : "+f"(c[0]), "+f"(c[1]), "+f"(c[2]), "+f"(c[3])
        : "r"(a0), "r"(a1), "r"(a2), "r"(a3), "r"(b0), "r"(b1));
}

__device__ __forceinline__ void cp16(uint32_t smem, const void* gmem) {
    asm volatile("cp.async.ca.shared.global [%0], [%1], 16;\n"
                 :: "r"(smem), "l"(gmem));
}
__device__ __forceinline__ void cp_commit() {
    asm volatile("cp.async.commit_group;\n" ::: "memory");
}
template <int N>
__device__ __forceinline__ void cp_wait() {
    asm volatile("cp.async.wait_group %0;\n" :: "n"(N) : "memory");
}

// ---------------------------------------------------------------------------
// Pre-round a buffer to tf32-valued fp32
// ---------------------------------------------------------------------------
__global__ __launch_bounds__(256) void cvt_tf32(
    const float4* __restrict__ in, float4* __restrict__ out, int n4)
{
    int i = blockIdx.x * blockDim.x + threadIdx.x;
    int stride = gridDim.x * blockDim.x;
    for (; i < n4; i += stride) {
        float4 v = in[i];
        float4 r;
        r.x = f2tff(v.x); r.y = f2tff(v.y);
        r.z = f2tff(v.z); r.w = f2tff(v.w);
        out[i] = r;
    }
}

// ===========================================================================
// TF32 tensor-core GEMM v3: C[m,n] = sum_k A[m,k]*Bt[n,k] + bias[n]
// Block 128x128x32, 256 threads = 8 warps, warp tile 64x32, 3-stage cp.async.
// Operands pre-rounded to tf32 grid -> inner loop pure LDS + MMA.
// mode 1: A=g_xt, scatter tf32 into g_qkv; mode 2: A=g_att, plain store.
// ===========================================================================
#define GBM 128
#define GBN 128
#define GBK 32
#define STG_FLOATS (GBM * GBK)                 // 4096 floats per A or B tile
#define STAGE_FLOATS (2 * STG_FLOATS)          // A+B per stage = 32KB
#define NSTAGE 3
#define SMEM_GEMM (NSTAGE * STAGE_FLOATS * 4)  // 96KB

__device__ __forceinline__ int swz(int r, int c) {
    return r * 32 + ((((c >> 2)) ^ (r & 7)) << 2) + (c & 3);
}

__global__ __launch_bounds__(256) void gemm_tc(
    const float* __restrict__ Bt,
    const float* __restrict__ bias, float* __restrict__ Cout,
    int M, int N, int K, int mode)
{
    extern __shared__ float smem[];
    const float* A = (mode == 2) ? g_att : g_xt;

    int tid = threadIdx.x, lane = tid & 31, w = tid >> 5;
    int wm0 = (w >> 2) * 64;      // 2 warps along M
    int wn0 = (w & 3) * 32;       // 4 warps along N
    int m0 = blockIdx.y * GBM, n0 = blockIdx.x * GBN;

    uint32_t smem_base = (uint32_t)__cvta_generic_to_shared(smem);

    float acc[4][4][4];
#pragma unroll
    for (int mt = 0; mt < 4; mt++)
#pragma unroll
        for (int nt = 0; nt < 4; nt++)
#pragma unroll
            for (int j = 0; j < 4; j++) acc[mt][nt][j] = 0.f;

    // staging: 4 chunks of A + 4 of B per thread per stage
    int srow[4], soff[4];
    const float* agp[4];
    const float* bgp[4];
#pragma unroll
    for (int it = 0; it < 4; it++) {
        int l = tid + it * 256;       // 0..1023
        int row = l >> 3, q = l & 7;
        srow[it] = row;
        soff[it] = (row * 32 + ((q ^ (row & 7)) << 2)) * 4;
        agp[it] = A  + (size_t)(m0 + row) * K + q * 4;
        bgp[it] = Bt + (size_t)(n0 + row) * K + q * 4;
    }

    int nK = K / GBK;

    // prologue: stages 0 and 1
#pragma unroll
    for (int s = 0; s < 2; s++) {
        uint32_t sA = smem_base + s * STAGE_FLOATS * 4;
        uint32_t sB = sA + STG_FLOATS * 4;
#pragma unroll
        for (int it = 0; it < 4; it++) {
            cp16(sA + soff[it], agp[it] + s * GBK);
            cp16(sB + soff[it], bgp[it] + s * GBK);
        }
        cp_commit();
    }

    int rd_stage = 0, wr_stage = 2;
    for (int kt = 0; kt < nK; kt++) {
        if (kt + 1 < nK) cp_wait<1>(); else cp_wait<0>();
        __syncthreads();

        // issue stage kt+2 (buffer last read 2 iterations ago, barrier-safe)
        if (kt + 2 < nK) {
            uint32_t sA = smem_base + wr_stage * STAGE_FLOATS * 4;
            uint32_t sB = sA + STG_FLOATS * 4;
            int kk = (kt + 2) * GBK;
#pragma unroll
            for (int it = 0; it < 4; it++) {
                cp16(sA + soff[it], agp[it] + kk);
                cp16(sB + soff[it], bgp[it] + kk);
            }
            cp_commit();
        }
        if (++wr_stage == NSTAGE) wr_stage = 0;

        const uint32_t* As = (const uint32_t*)(smem + (size_t)rd_stage * STAGE_FLOATS);
        const uint32_t* Bs = As + STG_FLOATS;
        if (++rd_stage == NSTAGE) rd_stage = 0;

#pragma unroll
        for (int kc = 0; kc < 4; kc++) {
            int c = kc * 8 + (lane & 3);
            uint32_t a[4][4];
#pragma unroll
            for (int mt = 0; mt < 4; mt++) {
                int r = wm0 + mt * 16 + (lane >> 2);
                a[mt][0] = As[swz(r,     c)];
                a[mt][1] = As[swz(r + 8, c)];
                a[mt][2] = As[swz(r,     c + 4)];
                a[mt][3] = As[swz(r + 8, c + 4)];
            }
#pragma unroll
            for (int nt = 0; nt < 4; nt++) {
                int n = wn0 + nt * 8 + (lane >> 2);
                uint32_t b0 = Bs[swz(n, c)];
                uint32_t b1 = Bs[swz(n, c + 4)];
#pragma unroll
                for (int mt = 0; mt < 4; mt++)
                    mma8(acc[mt][nt], a[mt][0], a[mt][1], a[mt][2], a[mt][3], b0, b1);
            }
        }
    }

    // Epilogue
#pragma unroll
    for (int mt = 0; mt < 4; mt++) {
#pragma unroll
        for (int h = 0; h < 2; h++) {
            int m = m0 + wm0 + mt * 16 + (lane >> 2) + h * 8;
#pragma unroll
            for (int nt = 0; nt < 4; nt++) {
                int n = n0 + wn0 + nt * 8 + 2 * (lane & 3);
                float2 r;
                r.x = acc[mt][nt][h * 2 + 0] + bias[n];
                r.y = acc[mt][nt][h * 2 + 1] + bias[n + 1];
                if (mode == 1) {
                    r.x = f2tff(r.x);
                    r.y = f2tff(r.y);
                    int which = n >> 10;
                    int hh = (n >> 6) & (HH - 1);
                    int d = n & (DD - 1);
                    int b = m >> 11;
                    int t = m & (TT - 1);
                    float* p = g_qkv + (size_t)which * BHTD
                             + ((((size_t)b * HH + hh) * TT + t) * DD + d);
                    *(float2*)p = r;
                } else {
                    *(float2*)(Cout + (size_t)m * N + n) = r;
                }
            }
        }
    }
}

// ===========================================================================
// Flash attention (causal), tf32 tensor cores, cp.async K/V double buffer.
// (unchanged from R4)
// ===========================================================================
#define KSD 68
#define VSD 72
#define KVSTG (64 * KSD + 64 * VSD)
#define SMEM_ATTN ((2 * KVSTG + 8 * 16 * KSD) * 4)

__global__ __launch_bounds__(256) void attn_tc()
{
    extern __shared__ float sm[];
    float* Psm = sm + 2 * KVSTG;

    int qb = gridDim.x - 1 - blockIdx.x;
    int bh = blockIdx.y;
    int q0 = qb * 128;
    int tid = threadIdx.x, lane = tid & 31, w = tid >> 5;
    int qw0 = q0 + w * 16;

    const float* qp = g_qkv + (size_t)bh * TT * DD;
    const float* kp = qp + (size_t)BHTD;
    const float* vp = qp + 2ull * BHTD;

    uint32_t smem_base = (uint32_t)__cvta_generic_to_shared(sm);

    int srow[4], sdq[4];
#pragma unroll
    for (int it = 0; it < 4; it++) {
        int l = tid + it * 256;
        srow[it] = l >> 4;
        sdq[it]  = (l & 15) * 4;
    }

    {
        uint32_t kb = smem_base;
        uint32_t vb = smem_base + 64 * KSD * 4;
#pragma unroll
        for (int it = 0; it < 4; it++) {
            int row = srow[it], dq = sdq[it];
            cp16(kb + (row * KSD + dq) * 4, kp + (size_t)row * DD + dq);
            cp16(vb + (row * VSD + dq) * 4, vp + (size_t)row * DD + dq);
        }
        cp_commit();
    }

    uint32_t qa[8][4];
    {
        int r = qw0 + (lane >> 2);
#pragma unroll
        for (int c = 0; c < 8; c++) {
            int col = c * 8 + (lane & 3);
            qa[c][0] = __float_as_uint(qp[(size_t)r * DD + col] * 0.125f);
            qa[c][1] = __float_as_uint(qp[(size_t)(r + 8) * DD + col] * 0.125f);
            qa[c][2] = __float_as_uint(qp[(size_t)r * DD + col + 4] * 0.125f);
            qa[c][3] = __float_as_uint(qp[(size_t)(r + 8) * DD + col + 4] * 0.125f);
        }
    }

    float m_i[2] = {-1e30f, -1e30f}, l_i[2] = {0.f, 0.f};
    float oacc[8][4];
#pragma unroll
    for (int nt = 0; nt < 8; nt++)
#pragma unroll
        for (int j = 0; j < 4; j++) oacc[nt][j] = 0.f;

    int jbmax = 2 * qb + 1;
    for (int jb = 0; jb <= jbmax; jb++) {
        int k0 = jb * 64;
        cp_wait<0>();
        __syncthreads();

        if (jb < jbmax) {
            int k1 = k0 + 64;
            uint32_t kb = smem_base + (size_t)((jb + 1) & 1) * KVSTG * 4;
            uint32_t vb = kb + 64 * KSD * 4;
#pragma unroll
            for (int it = 0; it < 4; it++) {
                int row = srow[it], dq = sdq[it];
                cp16(kb + (row * KSD + dq) * 4, kp + (size_t)(k1 + row) * DD + dq);
                cp16(vb + (row * VSD + dq) * 4, vp + (size_t)(k1 + row) * DD + dq);
            }
            cp_commit();
        }

        const uint32_t* Ku = (const uint32_t*)(sm + (size_t)(jb & 1) * KVSTG);
        const uint32_t* Vu = Ku + 64 * KSD;

        if (k0 <= qw0 + 15) {
            float sacc[8][4];
#pragma unroll
            for (int nt = 0; nt < 8; nt++)
#pragma unroll
                for (int j = 0; j < 4; j++) sacc[nt][j] = 0.f;
#pragma unroll
            for (int kc = 0; kc < 8; kc++) {
#pragma unroll
                for (int nt = 0; nt < 8; nt++) {
                    uint32_t b0 = Ku[(nt * 8 + (lane >> 2)) * KSD + kc * 8 + (lane & 3)];
                    uint32_t b1 = Ku[(nt * 8 + (lane >> 2)) * KSD + kc * 8 + 4 + (lane & 3)];
                    mma8(sacc[nt], qa[kc][0], qa[kc][1], qa[kc][2], qa[kc][3], b0, b1);
                }
            }

            if (k0 + 63 > qw0) {
                int r0 = qw0 + (lane >> 2);
#pragma unroll
                for (int nt = 0; nt < 8; nt++) {
                    int col = k0 + nt * 8 + 2 * (lane & 3);
                    if (col     > r0)     sacc[nt][0] = -1e30f;
                    if (col + 1 > r0)     sacc[nt][1] = -1e30f;
                    if (col     > r0 + 8) sacc[nt][2] = -1e30f;
                    if (col + 1 > r0 + 8) sacc[nt][3] = -1e30f;
                }
            }

#pragma unroll
            for (int h = 0; h < 2; h++) {
                float mx = -1e30f;
#pragma unroll
                for (int nt = 0; nt < 8; nt++) {
                    mx = fmaxf(mx, sacc[nt][h * 2 + 0]);
                    mx = fmaxf(mx, sacc[nt][h * 2 + 1]);
                }
                mx = fmaxf(mx, __shfl_xor_sync(0xffffffffu, mx, 1));
                mx = fmaxf(mx, __shfl_xor_sync(0xffffffffu, mx, 2));
                float mnew = fmaxf(m_i[h], mx);
                float alpha = __expf(m_i[h] - mnew);
                float rs = 0.f;
#pragma unroll
                for (int nt = 0; nt < 8; nt++) {
                    float p0 = __expf(sacc[nt][h * 2 + 0] - mnew);
                    float p1 = __expf(sacc[nt][h * 2 + 1] - mnew);
                    sacc[nt][h * 2 + 0] = p0;
                    sacc[nt][h * 2 + 1] = p1;
                    rs += p0 + p1;
                }
                rs += __shfl_xor_sync(0xffffffffu, rs, 1);
                rs += __shfl_xor_sync(0xffffffffu, rs, 2);
                l_i[h] = l_i[h] * alpha + rs;
                m_i[h] = mnew;
#pragma unroll
                for (int nt = 0; nt < 8; nt++) {
                    oacc[nt][h * 2 + 0] *= alpha;
                    oacc[nt][h * 2 + 1] *= alpha;
                }
            }

            float* Pw = Psm + w * 16 * KSD;
#pragma unroll
            for (int nt = 0; nt < 8; nt++) {
                int col = nt * 8 + 2 * (lane & 3);
                float2 p0, p1;
                p0.x = f2tff(sacc[nt][0]); p0.y = f2tff(sacc[nt][1]);
                p1.x = f2tff(sacc[nt][2]); p1.y = f2tff(sacc[nt][3]);
                *(float2*)&Pw[(lane >> 2) * KSD + col] = p0;
                *(float2*)&Pw[((lane >> 2) + 8) * KSD + col] = p1;
            }
            __syncwarp();
            const uint32_t* Pwu = (const uint32_t*)Pw;
#pragma unroll
            for (int kc = 0; kc < 8; kc++) {
                uint32_t a0 = Pwu[(lane >> 2) * KSD + kc * 8 + (lane & 3)];
                uint32_t a1 = Pwu[((lane >> 2) + 8) * KSD + kc * 8 + (lane & 3)];
                uint32_t a2 = Pwu[(lane >> 2) * KSD + kc * 8 + 4 + (lane & 3)];
                uint32_t a3 = Pwu[((lane >> 2) + 8) * KSD + kc * 8 + 4 + (lane & 3)];
#pragma unroll
                for (int nt = 0; nt < 8; nt++) {
                    uint32_t b0 = Vu[(kc * 8 + (lane & 3)) * VSD + nt * 8 + (lane >> 2)];
                    uint32_t b1 = Vu[(kc * 8 + 4 + (lane & 3)) * VSD + nt * 8 + (lane >> 2)];
                    mma8(oacc[nt], a0, a1, a2, a3, b0, b1);
                }
            }
        }
        __syncthreads();
    }

    int bb = bh >> 4, hh = bh & (HH - 1);
#pragma unroll
    for (int h = 0; h < 2; h++) {
        int row = qw0 + (lane >> 2) + h * 8;
        float inv = 1.f / l_i[h];
#pragma unroll
        for (int nt = 0; nt < 8; nt++) {
            int col = hh * DD + nt * 8 + 2 * (lane & 3);
            float2 r;
            r.x = f2tff(oacc[nt][h * 2 + 0] * inv);
            r.y = f2tff(oacc[nt][h * 2 + 1] * inv);
            *(float2*)(g_att + ((size_t)bb * TT + row) * CC + col) = r;
        }
    }
}

// ===========================================================================
// Launch
// ===========================================================================
extern "C" void kernel_launch(void* const* d_in, const int* in_sizes, int n_in,
                              void* d_out, int out_size)
{
    (void)in_sizes; (void)n_in; (void)out_size;
    const float* x      = (const float*)d_in[0];
    const float* qkv_w  = (const float*)d_in[1];
    const float* qkv_b  = (const float*)d_in[2];
    const float* proj_w = (const float*)d_in[3];
    const float* proj_b = (const float*)d_in[4];
    float* out = (float*)d_out;

    cudaFuncSetAttribute(gemm_tc,
                         cudaFuncAttributeMaxDynamicSharedMemorySize, SMEM_GEMM);
    cudaFuncSetAttribute(attn_tc,
                         cudaFuncAttributeMaxDynamicSharedMemorySize, SMEM_ATTN);

    float* xt; float* wq; float* wp;
    cudaGetSymbolAddress((void**)&xt, g_xt);
    cudaGetSymbolAddress((void**)&wq, g_wqkv);
    cudaGetSymbolAddress((void**)&wp, g_wproj);

    // 0) pre-round operands to tf32 grid
    cvt_tf32<<<2048, 256>>>((const float4*)x,      (float4*)xt, BB * TT * CC / 4);
    cvt_tf32<<<1024, 256>>>((const float4*)qkv_w,  (float4*)wq, 3 * CC * CC / 4);
    cvt_tf32<<<512,  256>>>((const float4*)proj_w, (float4*)wp, CC * CC / 4);

    // 1) QKV projection + bias -> scatter tf32 [3][B,H,T,D]
    gemm_tc<<<dim3(3 * CC / GBN, BB * TT / GBM), 256, SMEM_GEMM>>>(
        wq, qkv_b, nullptr, BB * TT, 3 * CC, CC, 1);

    // 2) Causal flash attention -> g_att [B,T,C]
    attn_tc<<<dim3(TT / 128, BB * HH), 256, SMEM_ATTN>>>();

    // 3) Output projection + bias -> d_out
    gemm_tc<<<dim3(CC / GBN, BB * TT / GBM), 256, SMEM_GEMM>>>(
        wp, proj_b, out, BB * TT, CC, CC, 2);
}

// round 6
// speedup vs baseline: 1.0494x; 1.0494x over previous
#include <cuda_runtime.h>
#include <cuda_bf16.h>
#include <stdint.h>
#include <math.h>

// Problem constants
#define BB   4
#define TT   2048
#define CC   1024
#define HH   16
#define DD   64
#define BHTD (BB * HH * TT * DD)

// Scratch (device globals: alloc-free per harness rules)
__device__ float g_qkv[3ull * BHTD];            // [3][B,H,T,D] tf32-valued
__device__ float g_att[(size_t)BB * TT * CC];   // [B,T,C] tf32-valued
__device__ float g_xt[(size_t)BB * TT * CC];    // tf32(x)
__device__ float g_wqkv[3 * CC * CC];           // tf32(qkv_w)
__device__ float g_wproj[CC * CC];              // tf32(proj_w)

// ---------------------------------------------------------------------------
// tf32 / mma / cp.async helpers
// ---------------------------------------------------------------------------
__device__ __forceinline__ uint32_t f2tf(float x) {
    uint32_t u;
    asm("cvt.rna.tf32.f32 %0, %1;" : "=r"(u) : "f"(x));
    return u;
}
__device__ __forceinline__ float f2tff(float x) { return __uint_as_float(f2tf(x)); }

__device__ __forceinline__ void mma8(float* c,
    uint32_t a0, uint32_t a1, uint32_t a2, uint32_t a3,
    uint32_t b0, uint32_t b1)
{
    asm volatile(
        "mma.sync.aligned.m16n8k8.row.col.f32.tf32.tf32.f32 "
        "{%0,%1,%2,%3},{%4,%5,%6,%7},{%8,%9},{%0,%1,%2,%3};"
        : "+f"(c[0]), "+f"(c[1]), "+f"(c[2]), "+f"(c[3])
        : "r"(a0), "r"(a1), "r"(a2), "r"(a3), "r"(b0), "r"(b1));
}

__device__ __forceinline__ void cp16(uint32_t smem, const void* gmem) {
    asm volatile("cp.async.ca.shared.global [%0], [%1], 16;\n"
                 :: "r"(smem), "l"(gmem));
}
__device__ __forceinline__ void cp_commit() {
    asm volatile("cp.async.commit_group;\n" ::: "memory");
}
template <int N>
__device__ __forceinline__ void cp_wait() {
    asm volatile("cp.async.wait_group %0;\n" :: "n"(N) : "memory");
}

// ---------------------------------------------------------------------------
// Pre-round a buffer to tf32-valued fp32
// ---------------------------------------------------------------------------
__global__ __launch_bounds__(256) void cvt_tf32(
    const float4* __restrict__ in, float4* __restrict__ out, int n4)
{
    int i = blockIdx.x * blockDim.x + threadIdx.x;
    int stride = gridDim.x * blockDim.x;
    for (; i < n4; i += stride) {
        float4 v = in[i];
        float4 r;
        r.x = f2tff(v.x); r.y = f2tff(v.y);
        r.z = f2tff(v.z); r.w = f2tff(v.w);
        out[i] = r;
    }
}

// ===========================================================================
// TF32 tensor-core GEMM v4: C[m,n] = sum_k A[m,k]*Bt[n,k] + bias[n]
// Block 128x128x32, 256 threads = 8 warps, warp tile 64x32, 3-stage cp.async.
// __launch_bounds__(256,2): 128 regs -> 2 CTAs/SM (192KB smem total).
// Hoisted swizzle bases: inner loop = LDS + MMA + 2 XORs per kc.
// mode 1: A=g_xt, scatter tf32 into g_qkv; mode 2: A=g_att, plain store.
// ===========================================================================
#define GBM 128
#define GBN 128
#define GBK 32
#define STG_FLOATS (GBM * GBK)
#define STAGE_FLOATS (2 * STG_FLOATS)
#define NSTAGE 3
#define SMEM_GEMM (NSTAGE * STAGE_FLOATS * 4)  // 96KB

__global__ __launch_bounds__(256, 2) void gemm_tc(
    const float* __restrict__ Bt,
    const float* __restrict__ bias, float* __restrict__ Cout,
    int M, int N, int K, int mode)
{
    extern __shared__ float smem[];
    const float* A = (mode == 2) ? g_att : g_xt;

    int tid = threadIdx.x, lane = tid & 31, w = tid >> 5;
    int wm0 = (w >> 2) * 64;      // 2 warps along M
    int wn0 = (w & 3) * 32;       // 4 warps along N
    int m0 = blockIdx.y * GBM, n0 = blockIdx.x * GBN;

    uint32_t smem_base = (uint32_t)__cvta_generic_to_shared(smem);

    float acc[4][4][4];
#pragma unroll
    for (int mt = 0; mt < 4; mt++)
#pragma unroll
        for (int nt = 0; nt < 4; nt++)
#pragma unroll
            for (int j = 0; j < 4; j++) acc[mt][nt][j] = 0.f;

    // staging: 4 chunks of A + 4 of B per thread per stage
    int soff[4];
    const float* agp[4];
    const float* bgp[4];
#pragma unroll
    for (int it = 0; it < 4; it++) {
        int l = tid + it * 256;
        int row = l >> 3, q = l & 7;
        soff[it] = (row * 32 + ((q ^ (row & 7)) << 2)) * 4;
        agp[it] = A  + (size_t)(m0 + row) * K + q * 4;
        bgp[it] = Bt + (size_t)(n0 + row) * K + q * 4;
    }

    // fragment-load bases (swizzle hoisted; key is mt/nt-invariant mod 8)
    int key = (lane >> 2) & 7;
    int arow[4], brow[4];
#pragma unroll
    for (int mt = 0; mt < 4; mt++)
        arow[mt] = (wm0 + mt * 16 + (lane >> 2)) * 32 + (lane & 3);
#pragma unroll
    for (int nt = 0; nt < 4; nt++)
        brow[nt] = (wn0 + nt * 8 + (lane >> 2)) * 32 + (lane & 3);

    int nK = K / GBK;

    // prologue: stages 0 and 1
#pragma unroll
    for (int s = 0; s < 2; s++) {
        uint32_t sA = smem_base + s * STAGE_FLOATS * 4;
        uint32_t sB = sA + STG_FLOATS * 4;
#pragma unroll
        for (int it = 0; it < 4; it++) {
            cp16(sA + soff[it], agp[it] + s * GBK);
            cp16(sB + soff[it], bgp[it] + s * GBK);
        }
        cp_commit();
    }

    int rd_stage = 0, wr_stage = 2;
    for (int kt = 0; kt < nK; kt++) {
        if (kt + 1 < nK) cp_wait<1>(); else cp_wait<0>();
        __syncthreads();

        if (kt + 2 < nK) {
            uint32_t sA = smem_base + wr_stage * STAGE_FLOATS * 4;
            uint32_t sB = sA + STG_FLOATS * 4;
            int kk = (kt + 2) * GBK;
#pragma unroll
            for (int it = 0; it < 4; it++) {
                cp16(sA + soff[it], agp[it] + kk);
                cp16(sB + soff[it], bgp[it] + kk);
            }
            cp_commit();
        }
        if (++wr_stage == NSTAGE) wr_stage = 0;

        const uint32_t* As = (const uint32_t*)(smem + (size_t)rd_stage * STAGE_FLOATS);
        const uint32_t* Bs = As + STG_FLOATS;
        if (++rd_stage == NSTAGE) rd_stage = 0;

#pragma unroll
        for (int kc = 0; kc < 4; kc++) {
            int x0 = ((2 * kc)     ^ key) << 2;
            int x1 = ((2 * kc + 1) ^ key) << 2;
            uint32_t a[4][4];
#pragma unroll
            for (int mt = 0; mt < 4; mt++) {
                a[mt][0] = As[arow[mt] + x0];
                a[mt][1] = As[arow[mt] + 256 + x0];
                a[mt][2] = As[arow[mt] + x1];
                a[mt][3] = As[arow[mt] + 256 + x1];
            }
#pragma unroll
            for (int nt = 0; nt < 4; nt++) {
                uint32_t b0 = Bs[brow[nt] + x0];
                uint32_t b1 = Bs[brow[nt] + x1];
#pragma unroll
                for (int mt = 0; mt < 4; mt++)
                    mma8(acc[mt][nt], a[mt][0], a[mt][1], a[mt][2], a[mt][3], b0, b1);
            }
        }
    }

    // Epilogue
#pragma unroll
    for (int mt = 0; mt < 4; mt++) {
#pragma unroll
        for (int h = 0; h < 2; h++) {
            int m = m0 + wm0 + mt * 16 + (lane >> 2) + h * 8;
#pragma unroll
            for (int nt = 0; nt < 4; nt++) {
                int n = n0 + wn0 + nt * 8 + 2 * (lane & 3);
                float2 r;
                r.x = acc[mt][nt][h * 2 + 0] + bias[n];
                r.y = acc[mt][nt][h * 2 + 1] + bias[n + 1];
                if (mode == 1) {
                    r.x = f2tff(r.x);
                    r.y = f2tff(r.y);
                    int which = n >> 10;
                    int hh = (n >> 6) & (HH - 1);
                    int d = n & (DD - 1);
                    int b = m >> 11;
                    int t = m & (TT - 1);
                    float* p = g_qkv + (size_t)which * BHTD
                             + ((((size_t)b * HH + hh) * TT + t) * DD + d);
                    *(float2*)p = r;
                } else {
                    *(float2*)(Cout + (size_t)m * N + n) = r;
                }
            }
        }
    }
}

// ===========================================================================
// Flash attention (causal), tf32 tensor cores, cp.async K/V double buffer.
// (unchanged)
// ===========================================================================
#define KSD 68
#define VSD 72
#define KVSTG (64 * KSD + 64 * VSD)
#define SMEM_ATTN ((2 * KVSTG + 8 * 16 * KSD) * 4)

__global__ __launch_bounds__(256) void attn_tc()
{
    extern __shared__ float sm[];
    float* Psm = sm + 2 * KVSTG;

    int qb = gridDim.x - 1 - blockIdx.x;
    int bh = blockIdx.y;
    int q0 = qb * 128;
    int tid = threadIdx.x, lane = tid & 31, w = tid >> 5;
    int qw0 = q0 + w * 16;

    const float* qp = g_qkv + (size_t)bh * TT * DD;
    const float* kp = qp + (size_t)BHTD;
    const float* vp = qp + 2ull * BHTD;

    uint32_t smem_base = (uint32_t)__cvta_generic_to_shared(sm);

    int srow[4], sdq[4];
#pragma unroll
    for (int it = 0; it < 4; it++) {
        int l = tid + it * 256;
        srow[it] = l >> 4;
        sdq[it]  = (l & 15) * 4;
    }

    {
        uint32_t kb = smem_base;
        uint32_t vb = smem_base + 64 * KSD * 4;
#pragma unroll
        for (int it = 0; it < 4; it++) {
            int row = srow[it], dq = sdq[it];
            cp16(kb + (row * KSD + dq) * 4, kp + (size_t)row * DD + dq);
            cp16(vb + (row * VSD + dq) * 4, vp + (size_t)row * DD + dq);
        }
        cp_commit();
    }

    uint32_t qa[8][4];
    {
        int r = qw0 + (lane >> 2);
#pragma unroll
        for (int c = 0; c < 8; c++) {
            int col = c * 8 + (lane & 3);
            qa[c][0] = __float_as_uint(qp[(size_t)r * DD + col] * 0.125f);
            qa[c][1] = __float_as_uint(qp[(size_t)(r + 8) * DD + col] * 0.125f);
            qa[c][2] = __float_as_uint(qp[(size_t)r * DD + col + 4] * 0.125f);
            qa[c][3] = __float_as_uint(qp[(size_t)(r + 8) * DD + col + 4] * 0.125f);
        }
    }

    float m_i[2] = {-1e30f, -1e30f}, l_i[2] = {0.f, 0.f};
    float oacc[8][4];
#pragma unroll
    for (int nt = 0; nt < 8; nt++)
#pragma unroll
        for (int j = 0; j < 4; j++) oacc[nt][j] = 0.f;

    int jbmax = 2 * qb + 1;
    for (int jb = 0; jb <= jbmax; jb++) {
        int k0 = jb * 64;
        cp_wait<0>();
        __syncthreads();

        if (jb < jbmax) {
            int k1 = k0 + 64;
            uint32_t kb = smem_base + (size_t)((jb + 1) & 1) * KVSTG * 4;
            uint32_t vb = kb + 64 * KSD * 4;
#pragma unroll
            for (int it = 0; it < 4; it++) {
                int row = srow[it], dq = sdq[it];
                cp16(kb + (row * KSD + dq) * 4, kp + (size_t)(k1 + row) * DD + dq);
                cp16(vb + (row * VSD + dq) * 4, vp + (size_t)(k1 + row) * DD + dq);
            }
            cp_commit();
        }

        const uint32_t* Ku = (const uint32_t*)(sm + (size_t)(jb & 1) * KVSTG);
        const uint32_t* Vu = Ku + 64 * KSD;

        if (k0 <= qw0 + 15) {
            float sacc[8][4];
#pragma unroll
            for (int nt = 0; nt < 8; nt++)
#pragma unroll
                for (int j = 0; j < 4; j++) sacc[nt][j] = 0.f;
#pragma unroll
            for (int kc = 0; kc < 8; kc++) {
#pragma unroll
                for (int nt = 0; nt < 8; nt++) {
                    uint32_t b0 = Ku[(nt * 8 + (lane >> 2)) * KSD + kc * 8 + (lane & 3)];
                    uint32_t b1 = Ku[(nt * 8 + (lane >> 2)) * KSD + kc * 8 + 4 + (lane & 3)];
                    mma8(sacc[nt], qa[kc][0], qa[kc][1], qa[kc][2], qa[kc][3], b0, b1);
                }
            }

            if (k0 + 63 > qw0) {
                int r0 = qw0 + (lane >> 2);
#pragma unroll
                for (int nt = 0; nt < 8; nt++) {
                    int col = k0 + nt * 8 + 2 * (lane & 3);
                    if (col     > r0)     sacc[nt][0] = -1e30f;
                    if (col + 1 > r0)     sacc[nt][1] = -1e30f;
                    if (col     > r0 + 8) sacc[nt][2] = -1e30f;
                    if (col + 1 > r0 + 8) sacc[nt][3] = -1e30f;
                }
            }

#pragma unroll
            for (int h = 0; h < 2; h++) {
                float mx = -1e30f;
#pragma unroll
                for (int nt = 0; nt < 8; nt++) {
                    mx = fmaxf(mx, sacc[nt][h * 2 + 0]);
                    mx = fmaxf(mx, sacc[nt][h * 2 + 1]);
                }
                mx = fmaxf(mx, __shfl_xor_sync(0xffffffffu, mx, 1));
                mx = fmaxf(mx, __shfl_xor_sync(0xffffffffu, mx, 2));
                float mnew = fmaxf(m_i[h], mx);
                float alpha = __expf(m_i[h] - mnew);
                float rs = 0.f;
#pragma unroll
                for (int nt = 0; nt < 8; nt++) {
                    float p0 = __expf(sacc[nt][h * 2 + 0] - mnew);
                    float p1 = __expf(sacc[nt][h * 2 + 1] - mnew);
                    sacc[nt][h * 2 + 0] = p0;
                    sacc[nt][h * 2 + 1] = p1;
                    rs += p0 + p1;
                }
                rs += __shfl_xor_sync(0xffffffffu, rs, 1);
                rs += __shfl_xor_sync(0xffffffffu, rs, 2);
                l_i[h] = l_i[h] * alpha + rs;
                m_i[h] = mnew;
#pragma unroll
                for (int nt = 0; nt < 8; nt++) {
                    oacc[nt][h * 2 + 0] *= alpha;
                    oacc[nt][h * 2 + 1] *= alpha;
                }
            }

            float* Pw = Psm + w * 16 * KSD;
#pragma unroll
            for (int nt = 0; nt < 8; nt++) {
                int col = nt * 8 + 2 * (lane & 3);
                float2 p0, p1;
                p0.x = f2tff(sacc[nt][0]); p0.y = f2tff(sacc[nt][1]);
                p1.x = f2tff(sacc[nt][2]); p1.y = f2tff(sacc[nt][3]);
                *(float2*)&Pw[(lane >> 2) * KSD + col] = p0;
                *(float2*)&Pw[((lane >> 2) + 8) * KSD + col] = p1;
            }
            __syncwarp();
            const uint32_t* Pwu = (const uint32_t*)Pw;
#pragma unroll
            for (int kc = 0; kc < 8; kc++) {
                uint32_t a0 = Pwu[(lane >> 2) * KSD + kc * 8 + (lane & 3)];
                uint32_t a1 = Pwu[((lane >> 2) + 8) * KSD + kc * 8 + (lane & 3)];
                uint32_t a2 = Pwu[(lane >> 2) * KSD + kc * 8 + 4 + (lane & 3)];
                uint32_t a3 = Pwu[((lane >> 2) + 8) * KSD + kc * 8 + 4 + (lane & 3)];
#pragma unroll
                for (int nt = 0; nt < 8; nt++) {
                    uint32_t b0 = Vu[(kc * 8 + (lane & 3)) * VSD + nt * 8 + (lane >> 2)];
                    uint32_t b1 = Vu[(kc * 8 + 4 + (lane & 3)) * VSD + nt * 8 + (lane >> 2)];
                    mma8(oacc[nt], a0, a1, a2, a3, b0, b1);
                }
            }
        }
        __syncthreads();
    }

    int bb = bh >> 4, hh = bh & (HH - 1);
#pragma unroll
    for (int h = 0; h < 2; h++) {
        int row = qw0 + (lane >> 2) + h * 8;
        float inv = 1.f / l_i[h];
#pragma unroll
        for (int nt = 0; nt < 8; nt++) {
            int col = hh * DD + nt * 8 + 2 * (lane & 3);
            float2 r;
            r.x = f2tff(oacc[nt][h * 2 + 0] * inv);
            r.y = f2tff(oacc[nt][h * 2 + 1] * inv);
            *(float2*)(g_att + ((size_t)bb * TT + row) * CC + col) = r;
        }
    }
}

// ===========================================================================
// Launch
// ===========================================================================
extern "C" void kernel_launch(void* const* d_in, const int* in_sizes, int n_in,
                              void* d_out, int out_size)
{
    (void)in_sizes; (void)n_in; (void)out_size;
    const float* x      = (const float*)d_in[0];
    const float* qkv_w  = (const float*)d_in[1];
    const float* qkv_b  = (const float*)d_in[2];
    const float* proj_w = (const float*)d_in[3];
    const float* proj_b = (const float*)d_in[4];
    float* out = (float*)d_out;

    cudaFuncSetAttribute(gemm_tc,
                         cudaFuncAttributeMaxDynamicSharedMemorySize, SMEM_GEMM);
    cudaFuncSetAttribute(attn_tc,
                         cudaFuncAttributeMaxDynamicSharedMemorySize, SMEM_ATTN);

    float* xt; float* wq; float* wp;
    cudaGetSymbolAddress((void**)&xt, g_xt);
    cudaGetSymbolAddress((void**)&wq, g_wqkv);
    cudaGetSymbolAddress((void**)&wp, g_wproj);

    // 0) pre-round operands to tf32 grid
    cvt_tf32<<<2048, 256>>>((const float4*)x,      (float4*)xt, BB * TT * CC / 4);
    cvt_tf32<<<1024, 256>>>((const float4*)qkv_w,  (float4*)wq, 3 * CC * CC / 4);
    cvt_tf32<<<512,  256>>>((const float4*)proj_w, (float4*)wp, CC * CC / 4);

    // 1) QKV projection + bias -> scatter tf32 [3][B,H,T,D]
    gemm_tc<<<dim3(3 * CC / GBN, BB * TT / GBM), 256, SMEM_GEMM>>>(
        wq, qkv_b, nullptr, BB * TT, 3 * CC, CC, 1);

    // 2) Causal flash attention -> g_att [B,T,C]
    attn_tc<<<dim3(TT / 128, BB * HH), 256, SMEM_ATTN>>>();

    // 3) Output projection + bias -> d_out
    gemm_tc<<<dim3(CC / GBN, BB * TT / GBM), 256, SMEM_GEMM>>>(
        wp, proj_b, out, BB * TT, CC, CC, 2);
}

// round 8
// speedup vs baseline: 1.1640x; 1.1092x over previous
#include <cuda_runtime.h>
#include <cuda_bf16.h>
#include <stdint.h>
#include <math.h>

// Problem constants
#define BB   4
#define TT   2048
#define CC   1024
#define HH   16
#define DD   64
#define BHTD (BB * HH * TT * DD)

// Scratch (device globals: alloc-free per harness rules)
__device__ float g_qkv[3ull * BHTD];            // [3][B,H,T,D] tf32-valued
__device__ float g_att[(size_t)BB * TT * CC];   // [B,T,C] tf32-valued
__device__ float g_xt[(size_t)BB * TT * CC];    // tf32(x)
__device__ float g_wqkv[3 * CC * CC];           // tf32(qkv_w)
__device__ float g_wproj[CC * CC];              // tf32(proj_w)

// ---------------------------------------------------------------------------
// tf32 / mma / cp.async helpers
// ---------------------------------------------------------------------------
__device__ __forceinline__ uint32_t f2tf(float x) {
    uint32_t u;
    asm("cvt.rna.tf32.f32 %0, %1;" : "=r"(u) : "f"(x));
    return u;
}
__device__ __forceinline__ float f2tff(float x) { return __uint_as_float(f2tf(x)); }

__device__ __forceinline__ void mma8(float* c,
    uint32_t a0, uint32_t a1, uint32_t a2, uint32_t a3,
    uint32_t b0, uint32_t b1)
{
    asm volatile(
        "mma.sync.aligned.m16n8k8.row.col.f32.tf32.tf32.f32 "
        "{%0,%1,%2,%3},{%4,%5,%6,%7},{%8,%9},{%0,%1,%2,%3};"
        : "+f"(c[0]), "+f"(c[1]), "+f"(c[2]), "+f"(c[3])
        : "r"(a0), "r"(a1), "r"(a2), "r"(a3), "r"(b0), "r"(b1));
}

__device__ __forceinline__ void cp16(uint32_t smem, const void* gmem) {
    asm volatile("cp.async.cg.shared.global [%0], [%1], 16;\n"
                 :: "r"(smem), "l"(gmem));
}
__device__ __forceinline__ void cp16ca(uint32_t smem, const void* gmem) {
    asm volatile("cp.async.ca.shared.global [%0], [%1], 16;\n"
                 :: "r"(smem), "l"(gmem));
}
__device__ __forceinline__ void cp_commit() {
    asm volatile("cp.async.commit_group;\n" ::: "memory");
}
template <int N>
__device__ __forceinline__ void cp_wait() {
    asm volatile("cp.async.wait_group %0;\n" :: "n"(N) : "memory");
}

// ---------------------------------------------------------------------------
// Pre-round a buffer to tf32-valued fp32
// ---------------------------------------------------------------------------
__global__ __launch_bounds__(256) void cvt_tf32(
    const float4* __restrict__ in, float4* __restrict__ out, int n4)
{
    int i = blockIdx.x * blockDim.x + threadIdx.x;
    int stride = gridDim.x * blockDim.x;
    for (; i < n4; i += stride) {
        float4 v = in[i];
        float4 r;
        r.x = f2tff(v.x); r.y = f2tff(v.y);
        r.z = f2tff(v.z); r.w = f2tff(v.w);
        out[i] = r;
    }
}

// ===========================================================================
// TF32 tensor-core GEMM v5: C[m,n] = sum_k A[m,k]*Bt[n,k] + bias[n]
// CTA tile 128x256x32, 256 threads = 8 warps, warp tile 64x64.
// Fragment reuse A:8x, B:4x -> 32 LDS : 32 MMA per warp per k-tile.
// 3-stage cp.async.cg ring, hoisted XOR-swizzle addressing.
// mode 1: A=g_xt, scatter tf32 into g_qkv; mode 2: A=g_att, plain store.
// ===========================================================================
#define GBM 128
#define GBN 256
#define GBK 32
#define A_FLOATS (GBM * GBK)                   // 4096
#define B_FLOATS (GBN * GBK)                   // 8192
#define STAGE_FLOATS (A_FLOATS + B_FLOATS)     // 12288 floats = 48KB
#define NSTAGE 3
#define SMEM_GEMM (NSTAGE * STAGE_FLOATS * 4)  // 144KB

__global__ __launch_bounds__(256, 1) void gemm_tc(
    const float* __restrict__ Bt,
    const float* __restrict__ bias, float* __restrict__ Cout,
    int M, int N, int K, int mode)
{
    extern __shared__ float smem[];
    const float* A = (mode == 2) ? g_att : g_xt;

    int tid = threadIdx.x, lane = tid & 31, w = tid >> 5;
    int wm0 = (w >> 2) * 64;      // 2 warps along M
    int wn0 = (w & 3) * 64;       // 4 warps along N
    int m0 = blockIdx.y * GBM, n0 = blockIdx.x * GBN;

    uint32_t smem_base = (uint32_t)__cvta_generic_to_shared(smem);

    float acc[4][8][4];
#pragma unroll
    for (int mt = 0; mt < 4; mt++)
#pragma unroll
        for (int nt = 0; nt < 8; nt++)
#pragma unroll
            for (int j = 0; j < 4; j++) acc[mt][nt][j] = 0.f;

    // staging: A 4 chunks/thread, B 8 chunks/thread per stage (16B each)
    int aoff[4]; const float* agp[4];
    int boff[8]; const float* bgp[8];
#pragma unroll
    for (int i = 0; i < 4; i++) {
        int l = tid + i * 256;                 // 0..1023
        int row = l >> 3, q = l & 7;
        aoff[i] = (row * 32 + ((q ^ (row & 7)) << 2)) * 4;
        agp[i]  = A + (size_t)(m0 + row) * K + q * 4;
    }
#pragma unroll
    for (int i = 0; i < 8; i++) {
        int l = tid + i * 256;                 // 0..2047
        int row = l >> 3, q = l & 7;
        boff[i] = (row * 32 + ((q ^ (row & 7)) << 2)) * 4;
        bgp[i]  = Bt + (size_t)(n0 + row) * K + q * 4;
    }

    // fragment-load bases (swizzle hoisted; row mod 8 key invariant across tiles)
    int key = (lane >> 2) & 7;
    int arow[4], brow[8];
#pragma unroll
    for (int mt = 0; mt < 4; mt++)
        arow[mt] = (wm0 + mt * 16 + (lane >> 2)) * 32 + (lane & 3);
#pragma unroll
    for (int nt = 0; nt < 8; nt++)
        brow[nt] = (wn0 + nt * 8 + (lane >> 2)) * 32 + (lane & 3);

    int nK = K / GBK;

    // prologue: stages 0 and 1
#pragma unroll
    for (int s = 0; s < 2; s++) {
        uint32_t sA = smem_base + s * STAGE_FLOATS * 4;
        uint32_t sB = sA + A_FLOATS * 4;
#pragma unroll
        for (int i = 0; i < 4; i++) cp16(sA + aoff[i], agp[i] + s * GBK);
#pragma unroll
        for (int i = 0; i < 8; i++) cp16(sB + boff[i], bgp[i] + s * GBK);
        cp_commit();
    }

    int rd_stage = 0, wr_stage = 2;
    for (int kt = 0; kt < nK; kt++) {
        if (kt + 1 < nK) cp_wait<1>(); else cp_wait<0>();
        __syncthreads();

        if (kt + 2 < nK) {
            uint32_t sA = smem_base + wr_stage * STAGE_FLOATS * 4;
            uint32_t sB = sA + A_FLOATS * 4;
            int kk = (kt + 2) * GBK;
#pragma unroll
            for (int i = 0; i < 4; i++) cp16(sA + aoff[i], agp[i] + kk);
#pragma unroll
            for (int i = 0; i < 8; i++) cp16(sB + boff[i], bgp[i] + kk);
            cp_commit();
        }
        if (++wr_stage == NSTAGE) wr_stage = 0;

        const uint32_t* As = (const uint32_t*)(smem + (size_t)rd_stage * STAGE_FLOATS);
        const uint32_t* Bs = As + A_FLOATS;
        if (++rd_stage == NSTAGE) rd_stage = 0;

#pragma unroll
        for (int kc = 0; kc < 4; kc++) {
            int x0 = ((2 * kc)     ^ key) << 2;
            int x1 = ((2 * kc + 1) ^ key) << 2;
            uint32_t a[4][4];
#pragma unroll
            for (int mt = 0; mt < 4; mt++) {
                a[mt][0] = As[arow[mt] + x0];
                a[mt][1] = As[arow[mt] + 256 + x0];
                a[mt][2] = As[arow[mt] + x1];
                a[mt][3] = As[arow[mt] + 256 + x1];
            }
#pragma unroll
            for (int nt = 0; nt < 8; nt++) {
                uint32_t b0 = Bs[brow[nt] + x0];
                uint32_t b1 = Bs[brow[nt] + x1];
#pragma unroll
                for (int mt = 0; mt < 4; mt++)
                    mma8(acc[mt][nt], a[mt][0], a[mt][1], a[mt][2], a[mt][3], b0, b1);
            }
        }
    }

    // Epilogue
#pragma unroll
    for (int mt = 0; mt < 4; mt++) {
#pragma unroll
        for (int h = 0; h < 2; h++) {
            int m = m0 + wm0 + mt * 16 + (lane >> 2) + h * 8;
#pragma unroll
            for (int nt = 0; nt < 8; nt++) {
                int n = n0 + wn0 + nt * 8 + 2 * (lane & 3);
                float2 r;
                r.x = acc[mt][nt][h * 2 + 0] + bias[n];
                r.y = acc[mt][nt][h * 2 + 1] + bias[n + 1];
                if (mode == 1) {
                    r.x = f2tff(r.x);
                    r.y = f2tff(r.y);
                    int which = n >> 10;
                    int hh = (n >> 6) & (HH - 1);
                    int d = n & (DD - 1);
                    int b = m >> 11;
                    int t = m & (TT - 1);
                    float* p = g_qkv + (size_t)which * BHTD
                             + ((((size_t)b * HH + hh) * TT + t) * DD + d);
                    *(float2*)p = r;
                } else {
                    *(float2*)(Cout + (size_t)m * N + n) = r;
                }
            }
        }
    }
}

// ===========================================================================
// Flash attention (causal), tf32 mma.sync, cp.async K/V double buffer.
// (unchanged from R6)
// ===========================================================================
#define KSD 68
#define VSD 72
#define KVSTG (64 * KSD + 64 * VSD)
#define SMEM_ATTN ((2 * KVSTG + 8 * 16 * KSD) * 4)

__global__ __launch_bounds__(256) void attn_tc()
{
    extern __shared__ float sm[];
    float* Psm = sm + 2 * KVSTG;

    int qb = gridDim.x - 1 - blockIdx.x;
    int bh = blockIdx.y;
    int q0 = qb * 128;
    int tid = threadIdx.x, lane = tid & 31, w = tid >> 5;
    int qw0 = q0 + w * 16;

    const float* qp = g_qkv + (size_t)bh * TT * DD;
    const float* kp = qp + (size_t)BHTD;
    const float* vp = qp + 2ull * BHTD;

    uint32_t smem_base = (uint32_t)__cvta_generic_to_shared(sm);

    int srow[4], sdq[4];
#pragma unroll
    for (int it = 0; it < 4; it++) {
        int l = tid + it * 256;
        srow[it] = l >> 4;
        sdq[it]  = (l & 15) * 4;
    }

    {
        uint32_t kb = smem_base;
        uint32_t vb = smem_base + 64 * KSD * 4;
#pragma unroll
        for (int it = 0; it < 4; it++) {
            int row = srow[it], dq = sdq[it];
            cp16ca(kb + (row * KSD + dq) * 4, kp + (size_t)row * DD + dq);
            cp16ca(vb + (row * VSD + dq) * 4, vp + (size_t)row * DD + dq);
        }
        cp_commit();
    }

    uint32_t qa[8][4];
    {
        int r = qw0 + (lane >> 2);
#pragma unroll
        for (int c = 0; c < 8; c++) {
            int col = c * 8 + (lane & 3);
            qa[c][0] = __float_as_uint(qp[(size_t)r * DD + col] * 0.125f);
            qa[c][1] = __float_as_uint(qp[(size_t)(r + 8) * DD + col] * 0.125f);
            qa[c][2] = __float_as_uint(qp[(size_t)r * DD + col + 4] * 0.125f);
            qa[c][3] = __float_as_uint(qp[(size_t)(r + 8) * DD + col + 4] * 0.125f);
        }
    }

    float m_i[2] = {-1e30f, -1e30f}, l_i[2] = {0.f, 0.f};
    float oacc[8][4];
#pragma unroll
    for (int nt = 0; nt < 8; nt++)
#pragma unroll
        for (int j = 0; j < 4; j++) oacc[nt][j] = 0.f;

    int jbmax = 2 * qb + 1;
    for (int jb = 0; jb <= jbmax; jb++) {
        int k0 = jb * 64;
        cp_wait<0>();
        __syncthreads();

        if (jb < jbmax) {
            int k1 = k0 + 64;
            uint32_t kb = smem_base + (size_t)((jb + 1) & 1) * KVSTG * 4;
            uint32_t vb = kb + 64 * KSD * 4;
#pragma unroll
            for (int it = 0; it < 4; it++) {
                int row = srow[it], dq = sdq[it];
                cp16ca(kb + (row * KSD + dq) * 4, kp + (size_t)(k1 + row) * DD + dq);
                cp16ca(vb + (row * VSD + dq) * 4, vp + (size_t)(k1 + row) * DD + dq);
            }
            cp_commit();
        }

        const uint32_t* Ku = (const uint32_t*)(sm + (size_t)(jb & 1) * KVSTG);
        const uint32_t* Vu = Ku + 64 * KSD;

        if (k0 <= qw0 + 15) {
            float sacc[8][4];
#pragma unroll
            for (int nt = 0; nt < 8; nt++)
#pragma unroll
                for (int j = 0; j < 4; j++) sacc[nt][j] = 0.f;
#pragma unroll
            for (int kc = 0; kc < 8; kc++) {
#pragma unroll
                for (int nt = 0; nt < 8; nt++) {
                    uint32_t b0 = Ku[(nt * 8 + (lane >> 2)) * KSD + kc * 8 + (lane & 3)];
                    uint32_t b1 = Ku[(nt * 8 + (lane >> 2)) * KSD + kc * 8 + 4 + (lane & 3)];
                    mma8(sacc[nt], qa[kc][0], qa[kc][1], qa[kc][2], qa[kc][3], b0, b1);
                }
            }

            if (k0 + 63 > qw0) {
                int r0 = qw0 + (lane >> 2);
#pragma unroll
                for (int nt = 0; nt < 8; nt++) {
                    int col = k0 + nt * 8 + 2 * (lane & 3);
                    if (col     > r0)     sacc[nt][0] = -1e30f;
                    if (col + 1 > r0)     sacc[nt][1] = -1e30f;
                    if (col     > r0 + 8) sacc[nt][2] = -1e30f;
                    if (col + 1 > r0 + 8) sacc[nt][3] = -1e30f;
                }
            }

#pragma unroll
            for (int h = 0; h < 2; h++) {
                float mx = -1e30f;
#pragma unroll
                for (int nt = 0; nt < 8; nt++) {
                    mx = fmaxf(mx, sacc[nt][h * 2 + 0]);
                    mx = fmaxf(mx, sacc[nt][h * 2 + 1]);
                }
                mx = fmaxf(mx, __shfl_xor_sync(0xffffffffu, mx, 1));
                mx = fmaxf(mx, __shfl_xor_sync(0xffffffffu, mx, 2));
                float mnew = fmaxf(m_i[h], mx);
                float alpha = __expf(m_i[h] - mnew);
                float rs = 0.f;
#pragma unroll
                for (int nt = 0; nt < 8; nt++) {
                    float p0 = __expf(sacc[nt][h * 2 + 0] - mnew);
                    float p1 = __expf(sacc[nt][h * 2 + 1] - mnew);
                    sacc[nt][h * 2 + 0] = p0;
                    sacc[nt][h * 2 + 1] = p1;
                    rs += p0 + p1;
                }
                rs += __shfl_xor_sync(0xffffffffu, rs, 1);
                rs += __shfl_xor_sync(0xffffffffu, rs, 2);
                l_i[h] = l_i[h] * alpha + rs;
                m_i[h] = mnew;
#pragma unroll
                for (int nt = 0; nt < 8; nt++) {
                    oacc[nt][h * 2 + 0] *= alpha;
                    oacc[nt][h * 2 + 1] *= alpha;
                }
            }

            float* Pw = Psm + w * 16 * KSD;
#pragma unroll
            for (int nt = 0; nt < 8; nt++) {
                int col = nt * 8 + 2 * (lane & 3);
                float2 p0, p1;
                p0.x = f2tff(sacc[nt][0]); p0.y = f2tff(sacc[nt][1]);
                p1.x = f2tff(sacc[nt][2]); p1.y = f2tff(sacc[nt][3]);
                *(float2*)&Pw[(lane >> 2) * KSD + col] = p0;
                *(float2*)&Pw[((lane >> 2) + 8) * KSD + col] = p1;
            }
            __syncwarp();
            const uint32_t* Pwu = (const uint32_t*)Pw;
#pragma unroll
            for (int kc = 0; kc < 8; kc++) {
                uint32_t a0 = Pwu[(lane >> 2) * KSD + kc * 8 + (lane & 3)];
                uint32_t a1 = Pwu[((lane >> 2) + 8) * KSD + kc * 8 + (lane & 3)];
                uint32_t a2 = Pwu[(lane >> 2) * KSD + kc * 8 + 4 + (lane & 3)];
                uint32_t a3 = Pwu[((lane >> 2) + 8) * KSD + kc * 8 + 4 + (lane & 3)];
#pragma unroll
                for (int nt = 0; nt < 8; nt++) {
                    uint32_t b0 = Vu[(kc * 8 + (lane & 3)) * VSD + nt * 8 + (lane >> 2)];
                    uint32_t b1 = Vu[(kc * 8 + 4 + (lane & 3)) * VSD + nt * 8 + (lane >> 2)];
                    mma8(oacc[nt], a0, a1, a2, a3, b0, b1);
                }
            }
        }
        __syncthreads();
    }

    int bb = bh >> 4, hh = bh & (HH - 1);
#pragma unroll
    for (int h = 0; h < 2; h++) {
        int row = qw0 + (lane >> 2) + h * 8;
        float inv = 1.f / l_i[h];
#pragma unroll
        for (int nt = 0; nt < 8; nt++) {
            int col = hh * DD + nt * 8 + 2 * (lane & 3);
            float2 r;
            r.x = f2tff(oacc[nt][h * 2 + 0] * inv);
            r.y = f2tff(oacc[nt][h * 2 + 1] * inv);
            *(float2*)(g_att + ((size_t)bb * TT + row) * CC + col) = r;
        }
    }
}

// ===========================================================================
// Launch
// ===========================================================================
extern "C" void kernel_launch(void* const* d_in, const int* in_sizes, int n_in,
                              void* d_out, int out_size)
{
    (void)in_sizes; (void)n_in; (void)out_size;
    const float* x      = (const float*)d_in[0];
    const float* qkv_w  = (const float*)d_in[1];
    const float* qkv_b  = (const float*)d_in[2];
    const float* proj_w = (const float*)d_in[3];
    const float* proj_b = (const float*)d_in[4];
    float* out = (float*)d_out;

    cudaFuncSetAttribute(gemm_tc,
                         cudaFuncAttributeMaxDynamicSharedMemorySize, SMEM_GEMM);
    cudaFuncSetAttribute(attn_tc,
                         cudaFuncAttributeMaxDynamicSharedMemorySize, SMEM_ATTN);

    float* xt; float* wq; float* wp;
    cudaGetSymbolAddress((void**)&xt, g_xt);
    cudaGetSymbolAddress((void**)&wq, g_wqkv);
    cudaGetSymbolAddress((void**)&wp, g_wproj);

    // 0) pre-round operands to tf32 grid
    cvt_tf32<<<2048, 256>>>((const float4*)x,      (float4*)xt, BB * TT * CC / 4);
    cvt_tf32<<<1024, 256>>>((const float4*)qkv_w,  (float4*)wq, 3 * CC * CC / 4);
    cvt_tf32<<<512,  256>>>((const float4*)proj_w, (float4*)wp, CC * CC / 4);

    // 1) QKV projection + bias -> scatter tf32 [3][B,H,T,D]
    gemm_tc<<<dim3(3 * CC / GBN, BB * TT / GBM), 256, SMEM_GEMM>>>(
        wq, qkv_b, nullptr, BB * TT, 3 * CC, CC, 1);

    // 2) Causal flash attention -> g_att [B,T,C]
    attn_tc<<<dim3(TT / 128, BB * HH), 256, SMEM_ATTN>>>();

    // 3) Output projection + bias -> d_out
    gemm_tc<<<dim3(CC / GBN, BB * TT / GBM), 256, SMEM_GEMM>>>(
        wp, proj_b, out, BB * TT, CC, CC, 2);
}

// round 9
// speedup vs baseline: 1.2258x; 1.0531x over previous
#include <cuda_runtime.h>
#include <cuda_bf16.h>
#include <stdint.h>
#include <math.h>

// Problem constants
#define BB   4
#define TT   2048
#define CC   1024
#define HH   16
#define DD   64
#define BHTD (BB * HH * TT * DD)

// Scratch (device globals: alloc-free per harness rules)
__device__ float g_qkv[3ull * BHTD];            // [3][B,H,T,D] tf32-valued
__device__ float g_att[(size_t)BB * TT * CC];   // [B,T,C] tf32-valued
__device__ float g_xt[(size_t)BB * TT * CC];    // tf32(x)
__device__ float g_wqkv[3 * CC * CC];           // tf32(qkv_w)
__device__ float g_wproj[CC * CC];              // tf32(proj_w)

// ---------------------------------------------------------------------------
// tf32 / mma / cp.async helpers
// ---------------------------------------------------------------------------
__device__ __forceinline__ uint32_t f2tf(float x) {
    uint32_t u;
    asm("cvt.rna.tf32.f32 %0, %1;" : "=r"(u) : "f"(x));
    return u;
}
__device__ __forceinline__ float f2tff(float x) { return __uint_as_float(f2tf(x)); }

__device__ __forceinline__ float ex2(float x) {
    float r;
    asm("ex2.approx.f32 %0, %1;" : "=f"(r) : "f"(x));
    return r;
}

__device__ __forceinline__ void mma8(float* c,
    uint32_t a0, uint32_t a1, uint32_t a2, uint32_t a3,
    uint32_t b0, uint32_t b1)
{
    asm volatile(
        "mma.sync.aligned.m16n8k8.row.col.f32.tf32.tf32.f32 "
        "{%0,%1,%2,%3},{%4,%5,%6,%7},{%8,%9},{%0,%1,%2,%3};"
        : "+f"(c[0]), "+f"(c[1]), "+f"(c[2]), "+f"(c[3])
        : "r"(a0), "r"(a1), "r"(a2), "r"(a3), "r"(b0), "r"(b1));
}

__device__ __forceinline__ void cp16(uint32_t smem, const void* gmem) {
    asm volatile("cp.async.cg.shared.global [%0], [%1], 16;\n"
                 :: "r"(smem), "l"(gmem));
}
__device__ __forceinline__ void cp16ca(uint32_t smem, const void* gmem) {
    asm volatile("cp.async.ca.shared.global [%0], [%1], 16;\n"
                 :: "r"(smem), "l"(gmem));
}
__device__ __forceinline__ void cp_commit() {
    asm volatile("cp.async.commit_group;\n" ::: "memory");
}
template <int N>
__device__ __forceinline__ void cp_wait() {
    asm volatile("cp.async.wait_group %0;\n" :: "n"(N) : "memory");
}

// ---------------------------------------------------------------------------
// Pre-round a buffer to tf32-valued fp32
// ---------------------------------------------------------------------------
__global__ __launch_bounds__(256) void cvt_tf32(
    const float4* __restrict__ in, float4* __restrict__ out, int n4)
{
    int i = blockIdx.x * blockDim.x + threadIdx.x;
    int stride = gridDim.x * blockDim.x;
    for (; i < n4; i += stride) {
        float4 v = in[i];
        float4 r;
        r.x = f2tff(v.x); r.y = f2tff(v.y);
        r.z = f2tff(v.z); r.w = f2tff(v.w);
        out[i] = r;
    }
}

// ===========================================================================
// TF32 tensor-core GEMM (unchanged from R8): CTA 128x256x32, 8 warps 64x64.
// ===========================================================================
#define GBM 128
#define GBN 256
#define GBK 32
#define A_FLOATS (GBM * GBK)
#define B_FLOATS (GBN * GBK)
#define STAGE_FLOATS (A_FLOATS + B_FLOATS)
#define NSTAGE 3
#define SMEM_GEMM (NSTAGE * STAGE_FLOATS * 4)

__global__ __launch_bounds__(256, 1) void gemm_tc(
    const float* __restrict__ Bt,
    const float* __restrict__ bias, float* __restrict__ Cout,
    int M, int N, int K, int mode)
{
    extern __shared__ float smem[];
    const float* A = (mode == 2) ? g_att : g_xt;

    int tid = threadIdx.x, lane = tid & 31, w = tid >> 5;
    int wm0 = (w >> 2) * 64;
    int wn0 = (w & 3) * 64;
    int m0 = blockIdx.y * GBM, n0 = blockIdx.x * GBN;

    uint32_t smem_base = (uint32_t)__cvta_generic_to_shared(smem);

    float acc[4][8][4];
#pragma unroll
    for (int mt = 0; mt < 4; mt++)
#pragma unroll
        for (int nt = 0; nt < 8; nt++)
#pragma unroll
            for (int j = 0; j < 4; j++) acc[mt][nt][j] = 0.f;

    int aoff[4]; const float* agp[4];
    int boff[8]; const float* bgp[8];
#pragma unroll
    for (int i = 0; i < 4; i++) {
        int l = tid + i * 256;
        int row = l >> 3, q = l & 7;
        aoff[i] = (row * 32 + ((q ^ (row & 7)) << 2)) * 4;
        agp[i]  = A + (size_t)(m0 + row) * K + q * 4;
    }
#pragma unroll
    for (int i = 0; i < 8; i++) {
        int l = tid + i * 256;
        int row = l >> 3, q = l & 7;
        boff[i] = (row * 32 + ((q ^ (row & 7)) << 2)) * 4;
        bgp[i]  = Bt + (size_t)(n0 + row) * K + q * 4;
    }

    int key = (lane >> 2) & 7;
    int arow[4], brow[8];
#pragma unroll
    for (int mt = 0; mt < 4; mt++)
        arow[mt] = (wm0 + mt * 16 + (lane >> 2)) * 32 + (lane & 3);
#pragma unroll
    for (int nt = 0; nt < 8; nt++)
        brow[nt] = (wn0 + nt * 8 + (lane >> 2)) * 32 + (lane & 3);

    int nK = K / GBK;

#pragma unroll
    for (int s = 0; s < 2; s++) {
        uint32_t sA = smem_base + s * STAGE_FLOATS * 4;
        uint32_t sB = sA + A_FLOATS * 4;
#pragma unroll
        for (int i = 0; i < 4; i++) cp16(sA + aoff[i], agp[i] + s * GBK);
#pragma unroll
        for (int i = 0; i < 8; i++) cp16(sB + boff[i], bgp[i] + s * GBK);
        cp_commit();
    }

    int rd_stage = 0, wr_stage = 2;
    for (int kt = 0; kt < nK; kt++) {
        if (kt + 1 < nK) cp_wait<1>(); else cp_wait<0>();
        __syncthreads();

        if (kt + 2 < nK) {
            uint32_t sA = smem_base + wr_stage * STAGE_FLOATS * 4;
            uint32_t sB = sA + A_FLOATS * 4;
            int kk = (kt + 2) * GBK;
#pragma unroll
            for (int i = 0; i < 4; i++) cp16(sA + aoff[i], agp[i] + kk);
#pragma unroll
            for (int i = 0; i < 8; i++) cp16(sB + boff[i], bgp[i] + kk);
            cp_commit();
        }
        if (++wr_stage == NSTAGE) wr_stage = 0;

        const uint32_t* As = (const uint32_t*)(smem + (size_t)rd_stage * STAGE_FLOATS);
        const uint32_t* Bs = As + A_FLOATS;
        if (++rd_stage == NSTAGE) rd_stage = 0;

#pragma unroll
        for (int kc = 0; kc < 4; kc++) {
            int x0 = ((2 * kc)     ^ key) << 2;
            int x1 = ((2 * kc + 1) ^ key) << 2;
            uint32_t a[4][4];
#pragma unroll
            for (int mt = 0; mt < 4; mt++) {
                a[mt][0] = As[arow[mt] + x0];
                a[mt][1] = As[arow[mt] + 256 + x0];
                a[mt][2] = As[arow[mt] + x1];
                a[mt][3] = As[arow[mt] + 256 + x1];
            }
#pragma unroll
            for (int nt = 0; nt < 8; nt++) {
                uint32_t b0 = Bs[brow[nt] + x0];
                uint32_t b1 = Bs[brow[nt] + x1];
#pragma unroll
                for (int mt = 0; mt < 4; mt++)
                    mma8(acc[mt][nt], a[mt][0], a[mt][1], a[mt][2], a[mt][3], b0, b1);
            }
        }
    }

#pragma unroll
    for (int mt = 0; mt < 4; mt++) {
#pragma unroll
        for (int h = 0; h < 2; h++) {
            int m = m0 + wm0 + mt * 16 + (lane >> 2) + h * 8;
#pragma unroll
            for (int nt = 0; nt < 8; nt++) {
                int n = n0 + wn0 + nt * 8 + 2 * (lane & 3);
                float2 r;
                r.x = acc[mt][nt][h * 2 + 0] + bias[n];
                r.y = acc[mt][nt][h * 2 + 1] + bias[n + 1];
                if (mode == 1) {
                    r.x = f2tff(r.x);
                    r.y = f2tff(r.y);
                    int which = n >> 10;
                    int hh = (n >> 6) & (HH - 1);
                    int d = n & (DD - 1);
                    int b = m >> 11;
                    int t = m & (TT - 1);
                    float* p = g_qkv + (size_t)which * BHTD
                             + ((((size_t)b * HH + hh) * TT + t) * DD + d);
                    *(float2*)p = r;
                } else {
                    *(float2*)(Cout + (size_t)m * N + n) = r;
                }
            }
        }
    }
}

// ===========================================================================
// Flash attention v2 (causal), tf32 mma.sync.
// Q-block 256, 8 warps x 32 rows (2 x 16-row groups) -> B-frag reuse 2x.
// Softmax in exp2 domain (scale 0.125*log2e folded into Q).
// cp.async K/V double buffer, k-tile 64.
// ===========================================================================
#define KSD 68
#define VSD 72
#define KVSTG (64 * KSD + 64 * VSD)
#define PSM_FLOATS (8 * 32 * KSD)
#define SMEM_ATTN ((2 * KVSTG + PSM_FLOATS) * 4)
#define QSCALE (0.125f * 1.44269504088896f)

__global__ __launch_bounds__(256) void attn_tc()
{
    extern __shared__ float sm[];
    float* Psm = sm + 2 * KVSTG;

    int qb = gridDim.x - 1 - blockIdx.x;
    int bh = blockIdx.y;
    int q0 = qb * 256;
    int tid = threadIdx.x, lane = tid & 31, w = tid >> 5;
    int qw0 = q0 + w * 32;

    const float* qp = g_qkv + (size_t)bh * TT * DD;
    const float* kp = qp + (size_t)BHTD;
    const float* vp = qp + 2ull * BHTD;

    uint32_t smem_base = (uint32_t)__cvta_generic_to_shared(sm);

    int srow[4], sdq[4];
#pragma unroll
    for (int it = 0; it < 4; it++) {
        int l = tid + it * 256;
        srow[it] = l >> 4;
        sdq[it]  = (l & 15) * 4;
    }

    // prologue: stage 0 <- k-block 0
    {
        uint32_t kb = smem_base;
        uint32_t vb = smem_base + 64 * KSD * 4;
#pragma unroll
        for (int it = 0; it < 4; it++) {
            int row = srow[it], dq = sdq[it];
            cp16ca(kb + (row * KSD + dq) * 4, kp + (size_t)row * DD + dq);
            cp16ca(vb + (row * VSD + dq) * 4, vp + (size_t)row * DD + dq);
        }
        cp_commit();
    }

    // Q -> registers, two 16-row groups, exp2-domain scale folded
    uint32_t qa[2][8][4];
#pragma unroll
    for (int g = 0; g < 2; g++) {
        int r = qw0 + g * 16 + (lane >> 2);
#pragma unroll
        for (int c = 0; c < 8; c++) {
            int col = c * 8 + (lane & 3);
            qa[g][c][0] = f2tf(qp[(size_t)r * DD + col] * QSCALE);
            qa[g][c][1] = f2tf(qp[(size_t)(r + 8) * DD + col] * QSCALE);
            qa[g][c][2] = f2tf(qp[(size_t)r * DD + col + 4] * QSCALE);
            qa[g][c][3] = f2tf(qp[(size_t)(r + 8) * DD + col + 4] * QSCALE);
        }
    }

    float m_i[2][2], l_i[2][2];
    float oacc[2][8][4];
#pragma unroll
    for (int g = 0; g < 2; g++) {
        m_i[g][0] = m_i[g][1] = -1e30f;
        l_i[g][0] = l_i[g][1] = 0.f;
#pragma unroll
        for (int nt = 0; nt < 8; nt++)
#pragma unroll
            for (int j = 0; j < 4; j++) oacc[g][nt][j] = 0.f;
    }

    int jbmax = 4 * qb + 3;
    for (int jb = 0; jb <= jbmax; jb++) {
        int k0 = jb * 64;
        cp_wait<0>();
        __syncthreads();

        if (jb < jbmax) {
            int k1 = k0 + 64;
            uint32_t kb = smem_base + (size_t)((jb + 1) & 1) * KVSTG * 4;
            uint32_t vb = kb + 64 * KSD * 4;
#pragma unroll
            for (int it = 0; it < 4; it++) {
                int row = srow[it], dq = sdq[it];
                cp16ca(kb + (row * KSD + dq) * 4, kp + (size_t)(k1 + row) * DD + dq);
                cp16ca(vb + (row * VSD + dq) * 4, vp + (size_t)(k1 + row) * DD + dq);
            }
            cp_commit();
        }

        const uint32_t* Ku = (const uint32_t*)(sm + (size_t)(jb & 1) * KVSTG);
        const uint32_t* Vu = Ku + 64 * KSD;

        if (k0 <= qw0 + 31) {
            // S = Q K^T (exp2 domain). B-frags shared across both row groups.
            float sacc[2][8][4];
#pragma unroll
            for (int g = 0; g < 2; g++)
#pragma unroll
                for (int nt = 0; nt < 8; nt++)
#pragma unroll
                    for (int j = 0; j < 4; j++) sacc[g][nt][j] = 0.f;
#pragma unroll
            for (int kc = 0; kc < 8; kc++) {
#pragma unroll
                for (int nt = 0; nt < 8; nt++) {
                    uint32_t b0 = Ku[(nt * 8 + (lane >> 2)) * KSD + kc * 8 + (lane & 3)];
                    uint32_t b1 = Ku[(nt * 8 + (lane >> 2)) * KSD + kc * 8 + 4 + (lane & 3)];
                    mma8(sacc[0][nt], qa[0][kc][0], qa[0][kc][1], qa[0][kc][2], qa[0][kc][3], b0, b1);
                    mma8(sacc[1][nt], qa[1][kc][0], qa[1][kc][1], qa[1][kc][2], qa[1][kc][3], b0, b1);
                }
            }

            // causal mask near diagonal
            if (k0 + 63 > qw0) {
#pragma unroll
                for (int g = 0; g < 2; g++) {
                    int r0 = qw0 + g * 16 + (lane >> 2);
#pragma unroll
                    for (int nt = 0; nt < 8; nt++) {
                        int col = k0 + nt * 8 + 2 * (lane & 3);
                        if (col     > r0)     sacc[g][nt][0] = -1e30f;
                        if (col + 1 > r0)     sacc[g][nt][1] = -1e30f;
                        if (col     > r0 + 8) sacc[g][nt][2] = -1e30f;
                        if (col + 1 > r0 + 8) sacc[g][nt][3] = -1e30f;
                    }
                }
            }

            // online softmax (exp2 domain)
#pragma unroll
            for (int g = 0; g < 2; g++) {
#pragma unroll
                for (int h = 0; h < 2; h++) {
                    float mx = -1e30f;
#pragma unroll
                    for (int nt = 0; nt < 8; nt++) {
                        mx = fmaxf(mx, sacc[g][nt][h * 2 + 0]);
                        mx = fmaxf(mx, sacc[g][nt][h * 2 + 1]);
                    }
                    mx = fmaxf(mx, __shfl_xor_sync(0xffffffffu, mx, 1));
                    mx = fmaxf(mx, __shfl_xor_sync(0xffffffffu, mx, 2));
                    float mnew = fmaxf(m_i[g][h], mx);
                    float alpha = ex2(m_i[g][h] - mnew);
                    float rs = 0.f;
#pragma unroll
                    for (int nt = 0; nt < 8; nt++) {
                        float p0 = ex2(sacc[g][nt][h * 2 + 0] - mnew);
                        float p1 = ex2(sacc[g][nt][h * 2 + 1] - mnew);
                        sacc[g][nt][h * 2 + 0] = p0;
                        sacc[g][nt][h * 2 + 1] = p1;
                        rs += p0 + p1;
                    }
                    rs += __shfl_xor_sync(0xffffffffu, rs, 1);
                    rs += __shfl_xor_sync(0xffffffffu, rs, 2);
                    l_i[g][h] = l_i[g][h] * alpha + rs;
                    m_i[g][h] = mnew;
#pragma unroll
                    for (int nt = 0; nt < 8; nt++) {
                        oacc[g][nt][h * 2 + 0] *= alpha;
                        oacc[g][nt][h * 2 + 1] *= alpha;
                    }
                }
            }

            // P -> per-warp smem (tf32) for A-fragment layout
            float* Pw = Psm + w * 32 * KSD;
#pragma unroll
            for (int g = 0; g < 2; g++) {
#pragma unroll
                for (int nt = 0; nt < 8; nt++) {
                    int col = nt * 8 + 2 * (lane & 3);
                    float2 p0, p1;
                    p0.x = f2tff(sacc[g][nt][0]); p0.y = f2tff(sacc[g][nt][1]);
                    p1.x = f2tff(sacc[g][nt][2]); p1.y = f2tff(sacc[g][nt][3]);
                    *(float2*)&Pw[(g * 16 + (lane >> 2)) * KSD + col] = p0;
                    *(float2*)&Pw[(g * 16 + (lane >> 2) + 8) * KSD + col] = p1;
                }
            }
            __syncwarp();
            const uint32_t* Pwu = (const uint32_t*)Pw;
#pragma unroll
            for (int kc = 0; kc < 8; kc++) {
                uint32_t a[2][4];
#pragma unroll
                for (int g = 0; g < 2; g++) {
                    a[g][0] = Pwu[(g * 16 + (lane >> 2)) * KSD + kc * 8 + (lane & 3)];
                    a[g][1] = Pwu[(g * 16 + (lane >> 2) + 8) * KSD + kc * 8 + (lane & 3)];
                    a[g][2] = Pwu[(g * 16 + (lane >> 2)) * KSD + kc * 8 + 4 + (lane & 3)];
                    a[g][3] = Pwu[(g * 16 + (lane >> 2) + 8) * KSD + kc * 8 + 4 + (lane & 3)];
                }
#pragma unroll
                for (int nt = 0; nt < 8; nt++) {
                    uint32_t b0 = Vu[(kc * 8 + (lane & 3)) * VSD + nt * 8 + (lane >> 2)];
                    uint32_t b1 = Vu[(kc * 8 + 4 + (lane & 3)) * VSD + nt * 8 + (lane >> 2)];
                    mma8(oacc[0][nt], a[0][0], a[0][1], a[0][2], a[0][3], b0, b1);
                    mma8(oacc[1][nt], a[1][0], a[1][1], a[1][2], a[1][3], b0, b1);
                }
            }
        }
        __syncthreads();
    }

    // normalize + store to g_att [B,T,C] (tf32-rounded for proj)
    int bb = bh >> 4, hh = bh & (HH - 1);
#pragma unroll
    for (int g = 0; g < 2; g++) {
#pragma unroll
        for (int h = 0; h < 2; h++) {
            int row = qw0 + g * 16 + (lane >> 2) + h * 8;
            float inv = 1.f / l_i[g][h];
#pragma unroll
            for (int nt = 0; nt < 8; nt++) {
                int col = hh * DD + nt * 8 + 2 * (lane & 3);
                float2 r;
                r.x = f2tff(oacc[g][nt][h * 2 + 0] * inv);
                r.y = f2tff(oacc[g][nt][h * 2 + 1] * inv);
                *(float2*)(g_att + ((size_t)bb * TT + row) * CC + col) = r;
            }
        }
    }
}

// ===========================================================================
// Launch
// ===========================================================================
extern "C" void kernel_launch(void* const* d_in, const int* in_sizes, int n_in,
                              void* d_out, int out_size)
{
    (void)in_sizes; (void)n_in; (void)out_size;
    const float* x      = (const float*)d_in[0];
    const float* qkv_w  = (const float*)d_in[1];
    const float* qkv_b  = (const float*)d_in[2];
    const float* proj_w = (const float*)d_in[3];
    const float* proj_b = (const float*)d_in[4];
    float* out = (float*)d_out;

    cudaFuncSetAttribute(gemm_tc,
                         cudaFuncAttributeMaxDynamicSharedMemorySize, SMEM_GEMM);
    cudaFuncSetAttribute(attn_tc,
                         cudaFuncAttributeMaxDynamicSharedMemorySize, SMEM_ATTN);

    float* xt; float* wq; float* wp;
    cudaGetSymbolAddress((void**)&xt, g_xt);
    cudaGetSymbolAddress((void**)&wq, g_wqkv);
    cudaGetSymbolAddress((void**)&wp, g_wproj);

    // 0) pre-round operands to tf32 grid
    cvt_tf32<<<2048, 256>>>((const float4*)x,      (float4*)xt, BB * TT * CC / 4);
    cvt_tf32<<<1024, 256>>>((const float4*)qkv_w,  (float4*)wq, 3 * CC * CC / 4);
    cvt_tf32<<<512,  256>>>((const float4*)proj_w, (float4*)wp, CC * CC / 4);

    // 1) QKV projection + bias -> scatter tf32 [3][B,H,T,D]
    gemm_tc<<<dim3(3 * CC / GBN, BB * TT / GBM), 256, SMEM_GEMM>>>(
        wq, qkv_b, nullptr, BB * TT, 3 * CC, CC, 1);

    // 2) Causal flash attention -> g_att [B,T,C]
    attn_tc<<<dim3(TT / 256, BB * HH), 256, SMEM_ATTN>>>();

    // 3) Output projection + bias -> d_out
    gemm_tc<<<dim3(CC / GBN, BB * TT / GBM), 256, SMEM_GEMM>>>(
        wp, proj_b, out, BB * TT, CC, CC, 2);
}

// round 10
// speedup vs baseline: 1.2259x; 1.0001x over previous
#include <cuda_runtime.h>
#include <cuda_bf16.h>
#include <stdint.h>
#include <math.h>

// Problem constants
#define BB   4
#define TT   2048
#define CC   1024
#define HH   16
#define DD   64
#define BHTD (BB * HH * TT * DD)

// Scratch (device globals: alloc-free per harness rules)
__device__ float g_qkv[3ull * BHTD];            // [3][B,H,T,D] tf32-valued
__device__ float g_att[(size_t)BB * TT * CC];   // [B,T,C] tf32-valued
__device__ float g_xt[(size_t)BB * TT * CC];    // tf32(x)
__device__ float g_wqkv[3 * CC * CC];           // tf32(qkv_w)
__device__ float g_wproj[CC * CC];              // tf32(proj_w)

// ---------------------------------------------------------------------------
// tf32 / mma / cp.async helpers
// ---------------------------------------------------------------------------
__device__ __forceinline__ uint32_t f2tf(float x) {
    uint32_t u;
    asm("cvt.rna.tf32.f32 %0, %1;" : "=r"(u) : "f"(x));
    return u;
}
__device__ __forceinline__ float f2tff(float x) { return __uint_as_float(f2tf(x)); }

__device__ __forceinline__ float ex2(float x) {
    float r;
    asm("ex2.approx.f32 %0, %1;" : "=f"(r) : "f"(x));
    return r;
}

__device__ __forceinline__ void mma8(float* c,
    uint32_t a0, uint32_t a1, uint32_t a2, uint32_t a3,
    uint32_t b0, uint32_t b1)
{
    asm volatile(
        "mma.sync.aligned.m16n8k8.row.col.f32.tf32.tf32.f32 "
        "{%0,%1,%2,%3},{%4,%5,%6,%7},{%8,%9},{%0,%1,%2,%3};"
        : "+f"(c[0]), "+f"(c[1]), "+f"(c[2]), "+f"(c[3])
        : "r"(a0), "r"(a1), "r"(a2), "r"(a3), "r"(b0), "r"(b1));
}

__device__ __forceinline__ void cp16(uint32_t smem, const void* gmem) {
    asm volatile("cp.async.cg.shared.global [%0], [%1], 16;\n"
                 :: "r"(smem), "l"(gmem));
}
__device__ __forceinline__ void cp16ca(uint32_t smem, const void* gmem) {
    asm volatile("cp.async.ca.shared.global [%0], [%1], 16;\n"
                 :: "r"(smem), "l"(gmem));
}
__device__ __forceinline__ void cp_commit() {
    asm volatile("cp.async.commit_group;\n" ::: "memory");
}
template <int N>
__device__ __forceinline__ void cp_wait() {
    asm volatile("cp.async.wait_group %0;\n" :: "n"(N) : "memory");
}

// ---------------------------------------------------------------------------
// Pre-round a buffer to tf32-valued fp32
// ---------------------------------------------------------------------------
__global__ __launch_bounds__(256) void cvt_tf32(
    const float4* __restrict__ in, float4* __restrict__ out, int n4)
{
    int i = blockIdx.x * blockDim.x + threadIdx.x;
    int stride = gridDim.x * blockDim.x;
    for (; i < n4; i += stride) {
        float4 v = in[i];
        float4 r;
        r.x = f2tff(v.x); r.y = f2tff(v.y);
        r.z = f2tff(v.z); r.w = f2tff(v.w);
        out[i] = r;
    }
}

// ===========================================================================
// TF32 tensor-core GEMM (unchanged from R8): CTA 128x256x32, 8 warps 64x64.
// ===========================================================================
#define GBM 128
#define GBN 256
#define GBK 32
#define A_FLOATS (GBM * GBK)
#define B_FLOATS (GBN * GBK)
#define STAGE_FLOATS (A_FLOATS + B_FLOATS)
#define NSTAGE 3
#define SMEM_GEMM (NSTAGE * STAGE_FLOATS * 4)

__global__ __launch_bounds__(256, 1) void gemm_tc(
    const float* __restrict__ Bt,
    const float* __restrict__ bias, float* __restrict__ Cout,
    int M, int N, int K, int mode)
{
    extern __shared__ float smem[];
    const float* A = (mode == 2) ? g_att : g_xt;

    int tid = threadIdx.x, lane = tid & 31, w = tid >> 5;
    int wm0 = (w >> 2) * 64;
    int wn0 = (w & 3) * 64;
    int m0 = blockIdx.y * GBM, n0 = blockIdx.x * GBN;

    uint32_t smem_base = (uint32_t)__cvta_generic_to_shared(smem);

    float acc[4][8][4];
#pragma unroll
    for (int mt = 0; mt < 4; mt++)
#pragma unroll
        for (int nt = 0; nt < 8; nt++)
#pragma unroll
            for (int j = 0; j < 4; j++) acc[mt][nt][j] = 0.f;

    int aoff[4]; const float* agp[4];
    int boff[8]; const float* bgp[8];
#pragma unroll
    for (int i = 0; i < 4; i++) {
        int l = tid + i * 256;
        int row = l >> 3, q = l & 7;
        aoff[i] = (row * 32 + ((q ^ (row & 7)) << 2)) * 4;
        agp[i]  = A + (size_t)(m0 + row) * K + q * 4;
    }
#pragma unroll
    for (int i = 0; i < 8; i++) {
        int l = tid + i * 256;
        int row = l >> 3, q = l & 7;
        boff[i] = (row * 32 + ((q ^ (row & 7)) << 2)) * 4;
        bgp[i]  = Bt + (size_t)(n0 + row) * K + q * 4;
    }

    int key = (lane >> 2) & 7;
    int arow[4], brow[8];
#pragma unroll
    for (int mt = 0; mt < 4; mt++)
        arow[mt] = (wm0 + mt * 16 + (lane >> 2)) * 32 + (lane & 3);
#pragma unroll
    for (int nt = 0; nt < 8; nt++)
        brow[nt] = (wn0 + nt * 8 + (lane >> 2)) * 32 + (lane & 3);

    int nK = K / GBK;

#pragma unroll
    for (int s = 0; s < 2; s++) {
        uint32_t sA = smem_base + s * STAGE_FLOATS * 4;
        uint32_t sB = sA + A_FLOATS * 4;
#pragma unroll
        for (int i = 0; i < 4; i++) cp16(sA + aoff[i], agp[i] + s * GBK);
#pragma unroll
        for (int i = 0; i < 8; i++) cp16(sB + boff[i], bgp[i] + s * GBK);
        cp_commit();
    }

    int rd_stage = 0, wr_stage = 2;
    for (int kt = 0; kt < nK; kt++) {
        if (kt + 1 < nK) cp_wait<1>(); else cp_wait<0>();
        __syncthreads();

        if (kt + 2 < nK) {
            uint32_t sA = smem_base + wr_stage * STAGE_FLOATS * 4;
            uint32_t sB = sA + A_FLOATS * 4;
            int kk = (kt + 2) * GBK;
#pragma unroll
            for (int i = 0; i < 4; i++) cp16(sA + aoff[i], agp[i] + kk);
#pragma unroll
            for (int i = 0; i < 8; i++) cp16(sB + boff[i], bgp[i] + kk);
            cp_commit();
        }
        if (++wr_stage == NSTAGE) wr_stage = 0;

        const uint32_t* As = (const uint32_t*)(smem + (size_t)rd_stage * STAGE_FLOATS);
        const uint32_t* Bs = As + A_FLOATS;
        if (++rd_stage == NSTAGE) rd_stage = 0;

#pragma unroll
        for (int kc = 0; kc < 4; kc++) {
            int x0 = ((2 * kc)     ^ key) << 2;
            int x1 = ((2 * kc + 1) ^ key) << 2;
            uint32_t a[4][4];
#pragma unroll
            for (int mt = 0; mt < 4; mt++) {
                a[mt][0] = As[arow[mt] + x0];
                a[mt][1] = As[arow[mt] + 256 + x0];
                a[mt][2] = As[arow[mt] + x1];
                a[mt][3] = As[arow[mt] + 256 + x1];
            }
#pragma unroll
            for (int nt = 0; nt < 8; nt++) {
                uint32_t b0 = Bs[brow[nt] + x0];
                uint32_t b1 = Bs[brow[nt] + x1];
#pragma unroll
                for (int mt = 0; mt < 4; mt++)
                    mma8(acc[mt][nt], a[mt][0], a[mt][1], a[mt][2], a[mt][3], b0, b1);
            }
        }
    }

#pragma unroll
    for (int mt = 0; mt < 4; mt++) {
#pragma unroll
        for (int h = 0; h < 2; h++) {
            int m = m0 + wm0 + mt * 16 + (lane >> 2) + h * 8;
#pragma unroll
            for (int nt = 0; nt < 8; nt++) {
                int n = n0 + wn0 + nt * 8 + 2 * (lane & 3);
                float2 r;
                r.x = acc[mt][nt][h * 2 + 0] + bias[n];
                r.y = acc[mt][nt][h * 2 + 1] + bias[n + 1];
                if (mode == 1) {
                    r.x = f2tff(r.x);
                    r.y = f2tff(r.y);
                    int which = n >> 10;
                    int hh = (n >> 6) & (HH - 1);
                    int d = n & (DD - 1);
                    int b = m >> 11;
                    int t = m & (TT - 1);
                    float* p = g_qkv + (size_t)which * BHTD
                             + ((((size_t)b * HH + hh) * TT + t) * DD + d);
                    *(float2*)p = r;
                } else {
                    *(float2*)(Cout + (size_t)m * N + n) = r;
                }
            }
        }
    }
}

// ===========================================================================
// Flash attention v3 (causal), tf32 mma.sync.
// Q-block 128, 128 threads = 4 warps x 32 rows, 2 CTAs/SM.
// P fed to PV MMA as raw fp32 (HW tf32 truncation) - no cvt in hot loop.
// Softmax in exp2 domain. cp.async K/V double buffer, k-tile 64.
// ===========================================================================
#define ATPB 128
#define KSD 68
#define VSD 72
#define KVSTG (64 * KSD + 64 * VSD)
#define PSM_FLOATS (4 * 32 * KSD)
#define SMEM_ATTN ((2 * KVSTG + PSM_FLOATS) * 4)   // ~106.5KB
#define QSCALE (0.125f * 1.44269504088896f)

__global__ __launch_bounds__(ATPB, 2) void attn_tc()
{
    extern __shared__ float sm[];
    float* Psm = sm + 2 * KVSTG;

    int qb = gridDim.x - 1 - blockIdx.x;     // big blocks first
    int bh = blockIdx.y;
    int q0 = qb * 128;
    int tid = threadIdx.x, lane = tid & 31, w = tid >> 5;
    int qw0 = q0 + w * 32;

    const float* qp = g_qkv + (size_t)bh * TT * DD;
    const float* kp = qp + (size_t)BHTD;
    const float* vp = qp + 2ull * BHTD;

    uint32_t smem_base = (uint32_t)__cvta_generic_to_shared(sm);

    // staging: 64 rows x 16 chunks for K and V, 8 chunks each per thread
    int srow[8], sdq[8];
#pragma unroll
    for (int it = 0; it < 8; it++) {
        int l = tid + it * ATPB;     // 0..1023
        srow[it] = l >> 4;
        sdq[it]  = (l & 15) * 4;
    }

    // prologue: stage 0 <- k-block 0
    {
        uint32_t kb = smem_base;
        uint32_t vb = smem_base + 64 * KSD * 4;
#pragma unroll
        for (int it = 0; it < 8; it++) {
            int row = srow[it], dq = sdq[it];
            cp16ca(kb + (row * KSD + dq) * 4, kp + (size_t)row * DD + dq);
            cp16ca(vb + (row * VSD + dq) * 4, vp + (size_t)row * DD + dq);
        }
        cp_commit();
    }

    // Q -> registers, two 16-row groups, exp2-domain scale folded
    uint32_t qa[2][8][4];
#pragma unroll
    for (int g = 0; g < 2; g++) {
        int r = qw0 + g * 16 + (lane >> 2);
#pragma unroll
        for (int c = 0; c < 8; c++) {
            int col = c * 8 + (lane & 3);
            qa[g][c][0] = f2tf(qp[(size_t)r * DD + col] * QSCALE);
            qa[g][c][1] = f2tf(qp[(size_t)(r + 8) * DD + col] * QSCALE);
            qa[g][c][2] = f2tf(qp[(size_t)r * DD + col + 4] * QSCALE);
            qa[g][c][3] = f2tf(qp[(size_t)(r + 8) * DD + col + 4] * QSCALE);
        }
    }

    float m_i[2][2], l_i[2][2];
    float oacc[2][8][4];
#pragma unroll
    for (int g = 0; g < 2; g++) {
        m_i[g][0] = m_i[g][1] = -1e30f;
        l_i[g][0] = l_i[g][1] = 0.f;
#pragma unroll
        for (int nt = 0; nt < 8; nt++)
#pragma unroll
            for (int j = 0; j < 4; j++) oacc[g][nt][j] = 0.f;
    }

    int jbmax = 2 * qb + 1;
    for (int jb = 0; jb <= jbmax; jb++) {
        int k0 = jb * 64;
        cp_wait<0>();
        __syncthreads();

        if (jb < jbmax) {
            int k1 = k0 + 64;
            uint32_t kb = smem_base + (size_t)((jb + 1) & 1) * KVSTG * 4;
            uint32_t vb = kb + 64 * KSD * 4;
#pragma unroll
            for (int it = 0; it < 8; it++) {
                int row = srow[it], dq = sdq[it];
                cp16ca(kb + (row * KSD + dq) * 4, kp + (size_t)(k1 + row) * DD + dq);
                cp16ca(vb + (row * VSD + dq) * 4, vp + (size_t)(k1 + row) * DD + dq);
            }
            cp_commit();
        }

        const uint32_t* Ku = (const uint32_t*)(sm + (size_t)(jb & 1) * KVSTG);
        const uint32_t* Vu = Ku + 64 * KSD;

        if (k0 <= qw0 + 31) {
            // S = Q K^T (exp2 domain). B-frags shared across both row groups.
            float sacc[2][8][4];
#pragma unroll
            for (int g = 0; g < 2; g++)
#pragma unroll
                for (int nt = 0; nt < 8; nt++)
#pragma unroll
                    for (int j = 0; j < 4; j++) sacc[g][nt][j] = 0.f;
#pragma unroll
            for (int kc = 0; kc < 8; kc++) {
#pragma unroll
                for (int nt = 0; nt < 8; nt++) {
                    uint32_t b0 = Ku[(nt * 8 + (lane >> 2)) * KSD + kc * 8 + (lane & 3)];
                    uint32_t b1 = Ku[(nt * 8 + (lane >> 2)) * KSD + kc * 8 + 4 + (lane & 3)];
                    mma8(sacc[0][nt], qa[0][kc][0], qa[0][kc][1], qa[0][kc][2], qa[0][kc][3], b0, b1);
                    mma8(sacc[1][nt], qa[1][kc][0], qa[1][kc][1], qa[1][kc][2], qa[1][kc][3], b0, b1);
                }
            }

            // causal mask near diagonal
            if (k0 + 63 > qw0) {
#pragma unroll
                for (int g = 0; g < 2; g++) {
                    int r0 = qw0 + g * 16 + (lane >> 2);
#pragma unroll
                    for (int nt = 0; nt < 8; nt++) {
                        int col = k0 + nt * 8 + 2 * (lane & 3);
                        if (col     > r0)     sacc[g][nt][0] = -1e30f;
                        if (col + 1 > r0)     sacc[g][nt][1] = -1e30f;
                        if (col     > r0 + 8) sacc[g][nt][2] = -1e30f;
                        if (col + 1 > r0 + 8) sacc[g][nt][3] = -1e30f;
                    }
                }
            }

            // online softmax (exp2 domain)
#pragma unroll
            for (int g = 0; g < 2; g++) {
#pragma unroll
                for (int h = 0; h < 2; h++) {
                    float mx = -1e30f;
#pragma unroll
                    for (int nt = 0; nt < 8; nt++) {
                        mx = fmaxf(mx, sacc[g][nt][h * 2 + 0]);
                        mx = fmaxf(mx, sacc[g][nt][h * 2 + 1]);
                    }
                    mx = fmaxf(mx, __shfl_xor_sync(0xffffffffu, mx, 1));
                    mx = fmaxf(mx, __shfl_xor_sync(0xffffffffu, mx, 2));
                    float mnew = fmaxf(m_i[g][h], mx);
                    float alpha = ex2(m_i[g][h] - mnew);
                    float rs = 0.f;
#pragma unroll
                    for (int nt = 0; nt < 8; nt++) {
                        float p0 = ex2(sacc[g][nt][h * 2 + 0] - mnew);
                        float p1 = ex2(sacc[g][nt][h * 2 + 1] - mnew);
                        sacc[g][nt][h * 2 + 0] = p0;
                        sacc[g][nt][h * 2 + 1] = p1;
                        rs += p0 + p1;
                    }
                    rs += __shfl_xor_sync(0xffffffffu, rs, 1);
                    rs += __shfl_xor_sync(0xffffffffu, rs, 2);
                    l_i[g][h] = l_i[g][h] * alpha + rs;
                    m_i[g][h] = mnew;
#pragma unroll
                    for (int nt = 0; nt < 8; nt++) {
                        oacc[g][nt][h * 2 + 0] *= alpha;
                        oacc[g][nt][h * 2 + 1] *= alpha;
                    }
                }
            }

            // P -> per-warp smem RAW fp32 (HW truncates to tf32 in MMA)
            float* Pw = Psm + w * 32 * KSD;
#pragma unroll
            for (int g = 0; g < 2; g++) {
#pragma unroll
                for (int nt = 0; nt < 8; nt++) {
                    int col = nt * 8 + 2 * (lane & 3);
                    float2 p0, p1;
                    p0.x = sacc[g][nt][0]; p0.y = sacc[g][nt][1];
                    p1.x = sacc[g][nt][2]; p1.y = sacc[g][nt][3];
                    *(float2*)&Pw[(g * 16 + (lane >> 2)) * KSD + col] = p0;
                    *(float2*)&Pw[(g * 16 + (lane >> 2) + 8) * KSD + col] = p1;
                }
            }
            __syncwarp();
            const uint32_t* Pwu = (const uint32_t*)Pw;
#pragma unroll
            for (int kc = 0; kc < 8; kc++) {
                uint32_t a[2][4];
#pragma unroll
                for (int g = 0; g < 2; g++) {
                    a[g][0] = Pwu[(g * 16 + (lane >> 2)) * KSD + kc * 8 + (lane & 3)];
                    a[g][1] = Pwu[(g * 16 + (lane >> 2) + 8) * KSD + kc * 8 + (lane & 3)];
                    a[g][2] = Pwu[(g * 16 + (lane >> 2)) * KSD + kc * 8 + 4 + (lane & 3)];
                    a[g][3] = Pwu[(g * 16 + (lane >> 2) + 8) * KSD + kc * 8 + 4 + (lane & 3)];
                }
#pragma unroll
                for (int nt = 0; nt < 8; nt++) {
                    uint32_t b0 = Vu[(kc * 8 + (lane & 3)) * VSD + nt * 8 + (lane >> 2)];
                    uint32_t b1 = Vu[(kc * 8 + 4 + (lane & 3)) * VSD + nt * 8 + (lane >> 2)];
                    mma8(oacc[0][nt], a[0][0], a[0][1], a[0][2], a[0][3], b0, b1);
                    mma8(oacc[1][nt], a[1][0], a[1][1], a[1][2], a[1][3], b0, b1);
                }
            }
        }
        __syncthreads();
    }

    // normalize + store to g_att [B,T,C] (tf32-rounded for proj)
    int bb = bh >> 4, hh = bh & (HH - 1);
#pragma unroll
    for (int g = 0; g < 2; g++) {
#pragma unroll
        for (int h = 0; h < 2; h++) {
            int row = qw0 + g * 16 + (lane >> 2) + h * 8;
            float inv = 1.f / l_i[g][h];
#pragma unroll
            for (int nt = 0; nt < 8; nt++) {
                int col = hh * DD + nt * 8 + 2 * (lane & 3);
                float2 r;
                r.x = f2tff(oacc[g][nt][h * 2 + 0] * inv);
                r.y = f2tff(oacc[g][nt][h * 2 + 1] * inv);
                *(float2*)(g_att + ((size_t)bb * TT + row) * CC + col) = r;
            }
        }
    }
}

// ===========================================================================
// Launch
// ===========================================================================
extern "C" void kernel_launch(void* const* d_in, const int* in_sizes, int n_in,
                              void* d_out, int out_size)
{
    (void)in_sizes; (void)n_in; (void)out_size;
    const float* x      = (const float*)d_in[0];
    const float* qkv_w  = (const float*)d_in[1];
    const float* qkv_b  = (const float*)d_in[2];
    const float* proj_w = (const float*)d_in[3];
    const float* proj_b = (const float*)d_in[4];
    float* out = (float*)d_out;

    cudaFuncSetAttribute(gemm_tc,
                         cudaFuncAttributeMaxDynamicSharedMemorySize, SMEM_GEMM);
    cudaFuncSetAttribute(attn_tc,
                         cudaFuncAttributeMaxDynamicSharedMemorySize, SMEM_ATTN);

    float* xt; float* wq; float* wp;
    cudaGetSymbolAddress((void**)&xt, g_xt);
    cudaGetSymbolAddress((void**)&wq, g_wqkv);
    cudaGetSymbolAddress((void**)&wp, g_wproj);

    // 0) pre-round operands to tf32 grid
    cvt_tf32<<<2048, 256>>>((const float4*)x,      (float4*)xt, BB * TT * CC / 4);
    cvt_tf32<<<1024, 256>>>((const float4*)qkv_w,  (float4*)wq, 3 * CC * CC / 4);
    cvt_tf32<<<512,  256>>>((const float4*)proj_w, (float4*)wp, CC * CC / 4);

    // 1) QKV projection + bias -> scatter tf32 [3][B,H,T,D]
    gemm_tc<<<dim3(3 * CC / GBN, BB * TT / GBM), 256, SMEM_GEMM>>>(
        wq, qkv_b, nullptr, BB * TT, 3 * CC, CC, 1);

    // 2) Causal flash attention -> g_att [B,T,C]
    attn_tc<<<dim3(TT / 128, BB * HH), ATPB, SMEM_ATTN>>>();

    // 3) Output projection + bias -> d_out
    gemm_tc<<<dim3(CC / GBN, BB * TT / GBM), 256, SMEM_GEMM>>>(
        wp, proj_b, out, BB * TT, CC, CC, 2);
}

// round 11
// speedup vs baseline: 1.2448x; 1.0154x over previous
#include <cuda_runtime.h>
#include <cuda_bf16.h>
#include <stdint.h>
#include <math.h>

// Problem constants
#define BB   4
#define TT   2048
#define CC   1024
#define HH   16
#define DD   64
#define BHTD (BB * HH * TT * DD)

// Scratch (device globals: alloc-free per harness rules)
__device__ float g_qkv[3ull * BHTD];            // [3][B,H,T,D] tf32-valued
__device__ float g_att[(size_t)BB * TT * CC];   // [B,T,C] tf32-valued
__device__ float g_xt[(size_t)BB * TT * CC];    // tf32(x)
__device__ float g_wqkv[3 * CC * CC];           // tf32(qkv_w)
__device__ float g_wproj[CC * CC];              // tf32(proj_w)

// ---------------------------------------------------------------------------
// tf32 / mma / ldmatrix / cp.async helpers
// ---------------------------------------------------------------------------
__device__ __forceinline__ uint32_t f2tf(float x) {
    uint32_t u;
    asm("cvt.rna.tf32.f32 %0, %1;" : "=r"(u) : "f"(x));
    return u;
}
__device__ __forceinline__ float f2tff(float x) { return __uint_as_float(f2tf(x)); }

__device__ __forceinline__ float ex2(float x) {
    float r;
    asm("ex2.approx.f32 %0, %1;" : "=f"(r) : "f"(x));
    return r;
}

__device__ __forceinline__ void mma8(float* c,
    uint32_t a0, uint32_t a1, uint32_t a2, uint32_t a3,
    uint32_t b0, uint32_t b1)
{
    asm volatile(
        "mma.sync.aligned.m16n8k8.row.col.f32.tf32.tf32.f32 "
        "{%0,%1,%2,%3},{%4,%5,%6,%7},{%8,%9},{%0,%1,%2,%3};"
        : "+f"(c[0]), "+f"(c[1]), "+f"(c[2]), "+f"(c[3])
        : "r"(a0), "r"(a1), "r"(a2), "r"(a3), "r"(b0), "r"(b1));
}

// ldmatrix x4: four 8x8 b16 tiles == four 8x4 tf32 fragment subtiles
__device__ __forceinline__ void ldsm4(uint32_t& r0, uint32_t& r1,
                                      uint32_t& r2, uint32_t& r3, uint32_t addr)
{
    asm volatile("ldmatrix.sync.aligned.m8n8.x4.shared.b16 {%0,%1,%2,%3}, [%4];"
                 : "=r"(r0), "=r"(r1), "=r"(r2), "=r"(r3) : "r"(addr));
}

__device__ __forceinline__ void cp16(uint32_t smem, const void* gmem) {
    asm volatile("cp.async.cg.shared.global [%0], [%1], 16;\n"
                 :: "r"(smem), "l"(gmem));
}
__device__ __forceinline__ void cp16ca(uint32_t smem, const void* gmem) {
    asm volatile("cp.async.ca.shared.global [%0], [%1], 16;\n"
                 :: "r"(smem), "l"(gmem));
}
__device__ __forceinline__ void cp_commit() {
    asm volatile("cp.async.commit_group;\n" ::: "memory");
}
template <int N>
__device__ __forceinline__ void cp_wait() {
    asm volatile("cp.async.wait_group %0;\n" :: "n"(N) : "memory");
}

// ---------------------------------------------------------------------------
// Pre-round a buffer to tf32-valued fp32
// ---------------------------------------------------------------------------
__global__ __launch_bounds__(256) void cvt_tf32(
    const float4* __restrict__ in, float4* __restrict__ out, int n4)
{
    int i = blockIdx.x * blockDim.x + threadIdx.x;
    int stride = gridDim.x * blockDim.x;
    for (; i < n4; i += stride) {
        float4 v = in[i];
        float4 r;
        r.x = f2tff(v.x); r.y = f2tff(v.y);
        r.z = f2tff(v.z); r.w = f2tff(v.w);
        out[i] = r;
    }
}

// ===========================================================================
// TF32 tensor-core GEMM v6: CTA 128x256x32, 8 warps 64x64, LDSM fragment loads.
// Per k-tile per warp: 32 LDSM.x4 + 128 HMMA (was 128 LDS.32 + 128 HMMA).
// ===========================================================================
#define GBM 128
#define GBN 256
#define GBK 32
#define A_FLOATS (GBM * GBK)
#define B_FLOATS (GBN * GBK)
#define STAGE_FLOATS (A_FLOATS + B_FLOATS)
#define NSTAGE 3
#define SMEM_GEMM (NSTAGE * STAGE_FLOATS * 4)

__global__ __launch_bounds__(256, 1) void gemm_tc(
    const float* __restrict__ Bt,
    const float* __restrict__ bias, float* __restrict__ Cout,
    int M, int N, int K, int mode)
{
    extern __shared__ float smem[];
    const float* A = (mode == 2) ? g_att : g_xt;

    int tid = threadIdx.x, lane = tid & 31, w = tid >> 5;
    int wm0 = (w >> 2) * 64;
    int wn0 = (w & 3) * 64;
    int m0 = blockIdx.y * GBM, n0 = blockIdx.x * GBN;

    uint32_t smem_base = (uint32_t)__cvta_generic_to_shared(smem);

    float acc[4][8][4];
#pragma unroll
    for (int mt = 0; mt < 4; mt++)
#pragma unroll
        for (int nt = 0; nt < 8; nt++)
#pragma unroll
            for (int j = 0; j < 4; j++) acc[mt][nt][j] = 0.f;

    // staging coords (cp.async)
    int aoff[4]; const float* agp[4];
    int boff[8]; const float* bgp[8];
#pragma unroll
    for (int i = 0; i < 4; i++) {
        int l = tid + i * 256;
        int row = l >> 3, q = l & 7;
        aoff[i] = (row * 32 + ((q ^ (row & 7)) << 2)) * 4;
        agp[i]  = A + (size_t)(m0 + row) * K + q * 4;
    }
#pragma unroll
    for (int i = 0; i < 8; i++) {
        int l = tid + i * 256;
        int row = l >> 3, q = l & 7;
        boff[i] = (row * 32 + ((q ^ (row & 7)) << 2)) * 4;
        bgp[i]  = Bt + (size_t)(n0 + row) * K + q * 4;
    }

    // ldmatrix per-thread row bases (bytes within tile) + swizzle params
    int keyx = lane & 7;
    int ha = lane >> 4;            // A: chunk half (0/1)
    int hb = (lane >> 3) & 1;      // B: chunk half (0/1)
    uint32_t aab[4], bab[4];
#pragma unroll
    for (int mt = 0; mt < 4; mt++)
        aab[mt] = (uint32_t)(wm0 + mt * 16 + (lane & 15)) * 128u;
#pragma unroll
    for (int p = 0; p < 4; p++)
        bab[p] = (uint32_t)(wn0 + p * 16 + (lane & 7) + ((lane >> 4) << 3)) * 128u;

    int nK = K / GBK;

#pragma unroll
    for (int s = 0; s < 2; s++) {
        uint32_t sA = smem_base + s * STAGE_FLOATS * 4;
        uint32_t sB = sA + A_FLOATS * 4;
#pragma unroll
        for (int i = 0; i < 4; i++) cp16(sA + aoff[i], agp[i] + s * GBK);
#pragma unroll
        for (int i = 0; i < 8; i++) cp16(sB + boff[i], bgp[i] + s * GBK);
        cp_commit();
    }

    int rd_stage = 0, wr_stage = 2;
    for (int kt = 0; kt < nK; kt++) {
        if (kt + 1 < nK) cp_wait<1>(); else cp_wait<0>();
        __syncthreads();

        if (kt + 2 < nK) {
            uint32_t sA = smem_base + wr_stage * STAGE_FLOATS * 4;
            uint32_t sB = sA + A_FLOATS * 4;
            int kk = (kt + 2) * GBK;
#pragma unroll
            for (int i = 0; i < 4; i++) cp16(sA + aoff[i], agp[i] + kk);
#pragma unroll
            for (int i = 0; i < 8; i++) cp16(sB + boff[i], bgp[i] + kk);
            cp_commit();
        }
        if (++wr_stage == NSTAGE) wr_stage = 0;

        uint32_t As_b = smem_base + rd_stage * STAGE_FLOATS * 4;
        uint32_t Bs_b = As_b + A_FLOATS * 4;
        if (++rd_stage == NSTAGE) rd_stage = 0;

#pragma unroll
        for (int kc = 0; kc < 4; kc++) {
            uint32_t ca = (uint32_t)(((2 * kc + ha) ^ keyx) << 4);
            uint32_t cb = (uint32_t)(((2 * kc + hb) ^ keyx) << 4);
            uint32_t a[4][4];
#pragma unroll
            for (int mt = 0; mt < 4; mt++)
                ldsm4(a[mt][0], a[mt][1], a[mt][2], a[mt][3], As_b + aab[mt] + ca);
#pragma unroll
            for (int p = 0; p < 4; p++) {
                uint32_t bv0, bv1, bv2, bv3;
                ldsm4(bv0, bv1, bv2, bv3, Bs_b + bab[p] + cb);
#pragma unroll
                for (int mt = 0; mt < 4; mt++) {
                    mma8(acc[mt][2 * p],     a[mt][0], a[mt][1], a[mt][2], a[mt][3], bv0, bv1);
                    mma8(acc[mt][2 * p + 1], a[mt][0], a[mt][1], a[mt][2], a[mt][3], bv2, bv3);
                }
            }
        }
    }

#pragma unroll
    for (int mt = 0; mt < 4; mt++) {
#pragma unroll
        for (int h = 0; h < 2; h++) {
            int m = m0 + wm0 + mt * 16 + (lane >> 2) + h * 8;
#pragma unroll
            for (int nt = 0; nt < 8; nt++) {
                int n = n0 + wn0 + nt * 8 + 2 * (lane & 3);
                float2 r;
                r.x = acc[mt][nt][h * 2 + 0] + bias[n];
                r.y = acc[mt][nt][h * 2 + 1] + bias[n + 1];
                if (mode == 1) {
                    r.x = f2tff(r.x);
                    r.y = f2tff(r.y);
                    int which = n >> 10;
                    int hh = (n >> 6) & (HH - 1);
                    int d = n & (DD - 1);
                    int b = m >> 11;
                    int t = m & (TT - 1);
                    float* p = g_qkv + (size_t)which * BHTD
                             + ((((size_t)b * HH + hh) * TT + t) * DD + d);
                    *(float2*)p = r;
                } else {
                    *(float2*)(Cout + (size_t)m * N + n) = r;
                }
            }
        }
    }
}

// ===========================================================================
// Flash attention v4 (causal): LDSM for K fragments in S-loop.
// Q-block 128, 128 threads = 4 warps x 32 rows, 2 CTAs/SM.
// ===========================================================================
#define ATPB 128
#define KSD 68
#define VSD 72
#define KVSTG (64 * KSD + 64 * VSD)
#define PSM_FLOATS (4 * 32 * KSD)
#define SMEM_ATTN ((2 * KVSTG + PSM_FLOATS) * 4)
#define QSCALE (0.125f * 1.44269504088896f)

__global__ __launch_bounds__(ATPB, 2) void attn_tc()
{
    extern __shared__ float sm[];
    float* Psm = sm + 2 * KVSTG;

    int qb = gridDim.x - 1 - blockIdx.x;
    int bh = blockIdx.y;
    int q0 = qb * 128;
    int tid = threadIdx.x, lane = tid & 31, w = tid >> 5;
    int qw0 = q0 + w * 32;

    const float* qp = g_qkv + (size_t)bh * TT * DD;
    const float* kp = qp + (size_t)BHTD;
    const float* vp = qp + 2ull * BHTD;

    uint32_t smem_base = (uint32_t)__cvta_generic_to_shared(sm);

    int srow[8], sdq[8];
#pragma unroll
    for (int it = 0; it < 8; it++) {
        int l = tid + it * ATPB;
        srow[it] = l >> 4;
        sdq[it]  = (l & 15) * 4;
    }

    {
        uint32_t kb = smem_base;
        uint32_t vb = smem_base + 64 * KSD * 4;
#pragma unroll
        for (int it = 0; it < 8; it++) {
            int row = srow[it], dq = sdq[it];
            cp16ca(kb + (row * KSD + dq) * 4, kp + (size_t)row * DD + dq);
            cp16ca(vb + (row * VSD + dq) * 4, vp + (size_t)row * DD + dq);
        }
        cp_commit();
    }

    // ldmatrix row bases for K fragments: p covers nt pair {2p, 2p+1}
    uint32_t krow[4];
#pragma unroll
    for (int p = 0; p < 4; p++) {
        int row = p * 16 + (lane & 7) + ((lane >> 4) << 3);
        krow[p] = (uint32_t)(row * KSD) * 4u + (uint32_t)(((lane >> 3) & 1) << 4);
    }

    uint32_t qa[2][8][4];
#pragma unroll
    for (int g = 0; g < 2; g++) {
        int r = qw0 + g * 16 + (lane >> 2);
#pragma unroll
        for (int c = 0; c < 8; c++) {
            int col = c * 8 + (lane & 3);
            qa[g][c][0] = f2tf(qp[(size_t)r * DD + col] * QSCALE);
            qa[g][c][1] = f2tf(qp[(size_t)(r + 8) * DD + col] * QSCALE);
            qa[g][c][2] = f2tf(qp[(size_t)r * DD + col + 4] * QSCALE);
            qa[g][c][3] = f2tf(qp[(size_t)(r + 8) * DD + col + 4] * QSCALE);
        }
    }

    float m_i[2][2], l_i[2][2];
    float oacc[2][8][4];
#pragma unroll
    for (int g = 0; g < 2; g++) {
        m_i[g][0] = m_i[g][1] = -1e30f;
        l_i[g][0] = l_i[g][1] = 0.f;
#pragma unroll
        for (int nt = 0; nt < 8; nt++)
#pragma unroll
            for (int j = 0; j < 4; j++) oacc[g][nt][j] = 0.f;
    }

    int jbmax = 2 * qb + 1;
    for (int jb = 0; jb <= jbmax; jb++) {
        int k0 = jb * 64;
        cp_wait<0>();
        __syncthreads();

        if (jb < jbmax) {
            int k1 = k0 + 64;
            uint32_t kb = smem_base + (size_t)((jb + 1) & 1) * KVSTG * 4;
            uint32_t vb = kb + 64 * KSD * 4;
#pragma unroll
            for (int it = 0; it < 8; it++) {
                int row = srow[it], dq = sdq[it];
                cp16ca(kb + (row * KSD + dq) * 4, kp + (size_t)(k1 + row) * DD + dq);
                cp16ca(vb + (row * VSD + dq) * 4, vp + (size_t)(k1 + row) * DD + dq);
            }
            cp_commit();
        }

        uint32_t Kb = smem_base + (uint32_t)((jb & 1) * KVSTG * 4);
        const uint32_t* Vu = (const uint32_t*)(sm + (size_t)(jb & 1) * KVSTG + 64 * KSD);

        if (k0 <= qw0 + 31) {
            // S = Q K^T: LDSM x4 per nt-pair per kc
            float sacc[2][8][4];
#pragma unroll
            for (int g = 0; g < 2; g++)
#pragma unroll
                for (int nt = 0; nt < 8; nt++)
#pragma unroll
                    for (int j = 0; j < 4; j++) sacc[g][nt][j] = 0.f;
#pragma unroll
            for (int kc = 0; kc < 8; kc++) {
#pragma unroll
                for (int p = 0; p < 4; p++) {
                    uint32_t b0, b1, b2, b3;
                    ldsm4(b0, b1, b2, b3, Kb + krow[p] + (uint32_t)(kc * 32));
                    mma8(sacc[0][2 * p],     qa[0][kc][0], qa[0][kc][1], qa[0][kc][2], qa[0][kc][3], b0, b1);
                    mma8(sacc[1][2 * p],     qa[1][kc][0], qa[1][kc][1], qa[1][kc][2], qa[1][kc][3], b0, b1);
                    mma8(sacc[0][2 * p + 1], qa[0][kc][0], qa[0][kc][1], qa[0][kc][2], qa[0][kc][3], b2, b3);
                    mma8(sacc[1][2 * p + 1], qa[1][kc][0], qa[1][kc][1], qa[1][kc][2], qa[1][kc][3], b2, b3);
                }
            }

            if (k0 + 63 > qw0) {
#pragma unroll
                for (int g = 0; g < 2; g++) {
                    int r0 = qw0 + g * 16 + (lane >> 2);
#pragma unroll
                    for (int nt = 0; nt < 8; nt++) {
                        int col = k0 + nt * 8 + 2 * (lane & 3);
                        if (col     > r0)     sacc[g][nt][0] = -1e30f;
                        if (col + 1 > r0)     sacc[g][nt][1] = -1e30f;
                        if (col     > r0 + 8) sacc[g][nt][2] = -1e30f;
                        if (col + 1 > r0 + 8) sacc[g][nt][3] = -1e30f;
                    }
                }
            }

#pragma unroll
            for (int g = 0; g < 2; g++) {
#pragma unroll
                for (int h = 0; h < 2; h++) {
                    float mx = -1e30f;
#pragma unroll
                    for (int nt = 0; nt < 8; nt++) {
                        mx = fmaxf(mx, sacc[g][nt][h * 2 + 0]);
                        mx = fmaxf(mx, sacc[g][nt][h * 2 + 1]);
                    }
                    mx = fmaxf(mx, __shfl_xor_sync(0xffffffffu, mx, 1));
                    mx = fmaxf(mx, __shfl_xor_sync(0xffffffffu, mx, 2));
                    float mnew = fmaxf(m_i[g][h], mx);
                    float alpha = ex2(m_i[g][h] - mnew);
                    float rs = 0.f;
#pragma unroll
                    for (int nt = 0; nt < 8; nt++) {
                        float p0 = ex2(sacc[g][nt][h * 2 + 0] - mnew);
                        float p1 = ex2(sacc[g][nt][h * 2 + 1] - mnew);
                        sacc[g][nt][h * 2 + 0] = p0;
                        sacc[g][nt][h * 2 + 1] = p1;
                        rs += p0 + p1;
                    }
                    rs += __shfl_xor_sync(0xffffffffu, rs, 1);
                    rs += __shfl_xor_sync(0xffffffffu, rs, 2);
                    l_i[g][h] = l_i[g][h] * alpha + rs;
                    m_i[g][h] = mnew;
#pragma unroll
                    for (int nt = 0; nt < 8; nt++) {
                        oacc[g][nt][h * 2 + 0] *= alpha;
                        oacc[g][nt][h * 2 + 1] *= alpha;
                    }
                }
            }

            // P -> per-warp smem RAW fp32 (HW truncates to tf32 in MMA)
            float* Pw = Psm + w * 32 * KSD;
#pragma unroll
            for (int g = 0; g < 2; g++) {
#pragma unroll
                for (int nt = 0; nt < 8; nt++) {
                    int col = nt * 8 + 2 * (lane & 3);
                    float2 p0, p1;
                    p0.x = sacc[g][nt][0]; p0.y = sacc[g][nt][1];
                    p1.x = sacc[g][nt][2]; p1.y = sacc[g][nt][3];
                    *(float2*)&Pw[(g * 16 + (lane >> 2)) * KSD + col] = p0;
                    *(float2*)&Pw[(g * 16 + (lane >> 2) + 8) * KSD + col] = p1;
                }
            }
            __syncwarp();
            const uint32_t* Pwu = (const uint32_t*)Pw;
#pragma unroll
            for (int kc = 0; kc < 8; kc++) {
                uint32_t a[2][4];
#pragma unroll
                for (int g = 0; g < 2; g++) {
                    a[g][0] = Pwu[(g * 16 + (lane >> 2)) * KSD + kc * 8 + (lane & 3)];
                    a[g][1] = Pwu[(g * 16 + (lane >> 2) + 8) * KSD + kc * 8 + (lane & 3)];
                    a[g][2] = Pwu[(g * 16 + (lane >> 2)) * KSD + kc * 8 + 4 + (lane & 3)];
                    a[g][3] = Pwu[(g * 16 + (lane >> 2) + 8) * KSD + kc * 8 + 4 + (lane & 3)];
                }
#pragma unroll
                for (int nt = 0; nt < 8; nt++) {
                    uint32_t b0 = Vu[(kc * 8 + (lane & 3)) * VSD + nt * 8 + (lane >> 2)];
                    uint32_t b1 = Vu[(kc * 8 + 4 + (lane & 3)) * VSD + nt * 8 + (lane >> 2)];
                    mma8(oacc[0][nt], a[0][0], a[0][1], a[0][2], a[0][3], b0, b1);
                    mma8(oacc[1][nt], a[1][0], a[1][1], a[1][2], a[1][3], b0, b1);
                }
            }
        }
        __syncthreads();
    }

    int bb = bh >> 4, hh = bh & (HH - 1);
#pragma unroll
    for (int g = 0; g < 2; g++) {
#pragma unroll
        for (int h = 0; h < 2; h++) {
            int row = qw0 + g * 16 + (lane >> 2) + h * 8;
            float inv = 1.f / l_i[g][h];
#pragma unroll
            for (int nt = 0; nt < 8; nt++) {
                int col = hh * DD + nt * 8 + 2 * (lane & 3);
                float2 r;
                r.x = f2tff(oacc[g][nt][h * 2 + 0] * inv);
                r.y = f2tff(oacc[g][nt][h * 2 + 1] * inv);
                *(float2*)(g_att + ((size_t)bb * TT + row) * CC + col) = r;
            }
        }
    }
}

// ===========================================================================
// Launch
// ===========================================================================
extern "C" void kernel_launch(void* const* d_in, const int* in_sizes, int n_in,
                              void* d_out, int out_size)
{
    (void)in_sizes; (void)n_in; (void)out_size;
    const float* x      = (const float*)d_in[0];
    const float* qkv_w  = (const float*)d_in[1];
    const float* qkv_b  = (const float*)d_in[2];
    const float* proj_w = (const float*)d_in[3];
    const float* proj_b = (const float*)d_in[4];
    float* out = (float*)d_out;

    cudaFuncSetAttribute(gemm_tc,
                         cudaFuncAttributeMaxDynamicSharedMemorySize, SMEM_GEMM);
    cudaFuncSetAttribute(attn_tc,
                         cudaFuncAttributeMaxDynamicSharedMemorySize, SMEM_ATTN);

    float* xt; float* wq; float* wp;
    cudaGetSymbolAddress((void**)&xt, g_xt);
    cudaGetSymbolAddress((void**)&wq, g_wqkv);
    cudaGetSymbolAddress((void**)&wp, g_wproj);

    // 0) pre-round operands to tf32 grid
    cvt_tf32<<<2048, 256>>>((const float4*)x,      (float4*)xt, BB * TT * CC / 4);
    cvt_tf32<<<1024, 256>>>((const float4*)qkv_w,  (float4*)wq, 3 * CC * CC / 4);
    cvt_tf32<<<512,  256>>>((const float4*)proj_w, (float4*)wp, CC * CC / 4);

    // 1) QKV projection + bias -> scatter tf32 [3][B,H,T,D]
    gemm_tc<<<dim3(3 * CC / GBN, BB * TT / GBM), 256, SMEM_GEMM>>>(
        wq, qkv_b, nullptr, BB * TT, 3 * CC, CC, 1);

    // 2) Causal flash attention -> g_att [B,T,C]
    attn_tc<<<dim3(TT / 128, BB * HH), ATPB, SMEM_ATTN>>>();

    // 3) Output projection + bias -> d_out
    gemm_tc<<<dim3(CC / GBN, BB * TT / GBM), 256, SMEM_GEMM>>>(
        wp, proj_b, out, BB * TT, CC, CC, 2);
}

// round 13
// speedup vs baseline: 1.2550x; 1.0082x over previous
#include <cuda_runtime.h>
#include <cuda_bf16.h>
#include <stdint.h>
#include <math.h>

// Problem constants
#define BB   4
#define TT   2048
#define CC   1024
#define HH   16
#define DD   64
#define BHTD (BB * HH * TT * DD)

// Scratch (device globals: alloc-free per harness rules)
__device__ float g_qkv[3ull * BHTD];            // [3][B,H,T,D] tf32-valued
__device__ float g_att[(size_t)BB * TT * CC];   // [B,T,C] tf32-valued
__device__ float g_xt[(size_t)BB * TT * CC];    // tf32(x)
__device__ float g_wqkv[3 * CC * CC];           // tf32(qkv_w)
__device__ float g_wproj[CC * CC];              // tf32(proj_w)

// ---------------------------------------------------------------------------
// tf32 / mma / ldmatrix / cp.async helpers
// ---------------------------------------------------------------------------
__device__ __forceinline__ uint32_t f2tf(float x) {
    uint32_t u;
    asm("cvt.rna.tf32.f32 %0, %1;" : "=r"(u) : "f"(x));
    return u;
}
__device__ __forceinline__ float f2tff(float x) { return __uint_as_float(f2tf(x)); }

__device__ __forceinline__ float ex2(float x) {
    float r;
    asm("ex2.approx.f32 %0, %1;" : "=f"(r) : "f"(x));
    return r;
}

__device__ __forceinline__ void mma8(float* c,
    uint32_t a0, uint32_t a1, uint32_t a2, uint32_t a3,
    uint32_t b0, uint32_t b1)
{
    asm volatile(
        "mma.sync.aligned.m16n8k8.row.col.f32.tf32.tf32.f32 "
        "{%0,%1,%2,%3},{%4,%5,%6,%7},{%8,%9},{%0,%1,%2,%3};"
        : "+f"(c[0]), "+f"(c[1]), "+f"(c[2]), "+f"(c[3])
        : "r"(a0), "r"(a1), "r"(a2), "r"(a3), "r"(b0), "r"(b1));
}

__device__ __forceinline__ void ldsm4(uint32_t& r0, uint32_t& r1,
                                      uint32_t& r2, uint32_t& r3, uint32_t addr)
{
    asm volatile("ldmatrix.sync.aligned.m8n8.x4.shared.b16 {%0,%1,%2,%3}, [%4];"
                 : "=r"(r0), "=r"(r1), "=r"(r2), "=r"(r3) : "r"(addr));
}

__device__ __forceinline__ void cp16(uint32_t smem, const void* gmem) {
    asm volatile("cp.async.cg.shared.global [%0], [%1], 16;\n"
                 :: "r"(smem), "l"(gmem));
}
__device__ __forceinline__ void cp16ca(uint32_t smem, const void* gmem) {
    asm volatile("cp.async.ca.shared.global [%0], [%1], 16;\n"
                 :: "r"(smem), "l"(gmem));
}
__device__ __forceinline__ void cp_commit() {
    asm volatile("cp.async.commit_group;\n" ::: "memory");
}
template <int N>
__device__ __forceinline__ void cp_wait() {
    asm volatile("cp.async.wait_group %0;\n" :: "n"(N) : "memory");
}

// ---------------------------------------------------------------------------
// Pre-round all three operand buffers to tf32-valued fp32 (one launch)
// ---------------------------------------------------------------------------
#define N4_X  (BB * TT * CC / 4)
#define N4_WQ (3 * CC * CC / 4)
#define N4_WP (CC * CC / 4)

__global__ __launch_bounds__(256) void cvt_all(
    const float4* __restrict__ x, const float4* __restrict__ wq,
    const float4* __restrict__ wp)
{
    float4* ox = (float4*)g_xt;
    float4* oq = (float4*)g_wqkv;
    float4* op = (float4*)g_wproj;
    int total = N4_X + N4_WQ + N4_WP;
    int i = blockIdx.x * blockDim.x + threadIdx.x;
    int stride = gridDim.x * blockDim.x;
    for (; i < total; i += stride) {
        const float4* in; float4* out; int j;
        if (i < N4_X)              { in = x;  out = ox; j = i; }
        else if (i < N4_X + N4_WQ) { in = wq; out = oq; j = i - N4_X; }
        else                       { in = wp; out = op; j = i - N4_X - N4_WQ; }
        float4 v = in[j];
        float4 r;
        r.x = f2tff(v.x); r.y = f2tff(v.y);
        r.z = f2tff(v.z); r.w = f2tff(v.w);
        out[j] = r;
    }
}

// ===========================================================================
// TF32 tensor-core GEMM v7: CTA 128x256x64, 8 warps 64x64, LDSM loads.
// GBK=64 2-stage ring (192KB smem) -> half the tile-boundary barriers.
// mode 1: A=g_xt, scatter tf32 into g_qkv; mode 2: A=g_att, plain store.
// ===========================================================================
#define GBM 128
#define GBN 256
#define GBK 64
#define A_FLOATS (GBM * GBK)                   // 8192
#define B_FLOATS (GBN * GBK)                   // 16384
#define STAGE_FLOATS (A_FLOATS + B_FLOATS)     // 24576 = 96KB
#define NSTAGE 2
#define SMEM_GEMM (NSTAGE * STAGE_FLOATS * 4)  // 192KB

__global__ __launch_bounds__(256, 1) void gemm_tc(
    const float* __restrict__ Bt,
    const float* __restrict__ bias, float* __restrict__ Cout,
    int M, int N, int K, int mode)
{
    extern __shared__ float smem[];
    const float* A = (mode == 2) ? g_att : g_xt;

    int tid = threadIdx.x, lane = tid & 31, w = tid >> 5;
    int wm0 = (w >> 2) * 64;
    int wn0 = (w & 3) * 64;
    int m0 = blockIdx.y * GBM, n0 = blockIdx.x * GBN;

    uint32_t smem_base = (uint32_t)__cvta_generic_to_shared(smem);

    float acc[4][8][4];
#pragma unroll
    for (int mt = 0; mt < 4; mt++)
#pragma unroll
        for (int nt = 0; nt < 8; nt++)
#pragma unroll
            for (int j = 0; j < 4; j++) acc[mt][nt][j] = 0.f;

    // ldmatrix per-thread bases (row stride 256B) + swizzle params
    int keyx = lane & 7;
    int ha = lane >> 4;            // A: chunk half
    int hb = (lane >> 3) & 1;      // B: chunk half
    uint32_t aab[4], bab[4];
#pragma unroll
    for (int mt = 0; mt < 4; mt++)
        aab[mt] = (uint32_t)(wm0 + mt * 16 + (lane & 15)) * 256u;
#pragma unroll
    for (int p = 0; p < 4; p++)
        bab[p] = (uint32_t)(wn0 + p * 16 + (lane & 7) + ((lane >> 4) << 3)) * 256u;

    int nK = K / GBK;

    // --- staging helper (24 cp.async per thread per tile) ---
    auto stage_tile = [&](int st, int kk) {
        uint32_t sA = smem_base + (uint32_t)st * (STAGE_FLOATS * 4);
        uint32_t sB = sA + A_FLOATS * 4;
#pragma unroll
        for (int i = 0; i < 8; i++) {            // A: 128 rows x 16 chunks
            int l = tid + i * 256;
            int row = l >> 4, q = l & 15;
            uint32_t soff = (uint32_t)row * 256u + (uint32_t)((q ^ (row & 7)) << 4);
            cp16(sA + soff, A + (size_t)(m0 + row) * K + kk + q * 4);
        }
#pragma unroll
        for (int i = 0; i < 16; i++) {           // B: 256 rows x 16 chunks
            int l = tid + i * 256;
            int row = l >> 4, q = l & 15;
            uint32_t soff = (uint32_t)row * 256u + (uint32_t)((q ^ (row & 7)) << 4);
            cp16(sB + soff, Bt + (size_t)(n0 + row) * K + kk + q * 4);
        }
        cp_commit();
    };

    // prologue: stage 0
    stage_tile(0, 0);

    for (int kt = 0; kt < nK; kt++) {
        cp_wait<0>();
        __syncthreads();     // stage kt visible; all done reading other buffer

        if (kt + 1 < nK) stage_tile((kt + 1) & 1, (kt + 1) * GBK);

        uint32_t As_b = smem_base + (uint32_t)(kt & 1) * (STAGE_FLOATS * 4);
        uint32_t Bs_b = As_b + A_FLOATS * 4;

#pragma unroll
        for (int kc = 0; kc < 8; kc++) {
            uint32_t ca = (uint32_t)(((2 * kc + ha) ^ keyx) << 4);
            uint32_t cb = (uint32_t)(((2 * kc + hb) ^ keyx) << 4);
            uint32_t a[4][4];
#pragma unroll
            for (int mt = 0; mt < 4; mt++)
                ldsm4(a[mt][0], a[mt][1], a[mt][2], a[mt][3], As_b + aab[mt] + ca);
#pragma unroll
            for (int p = 0; p < 4; p++) {
                uint32_t bv0, bv1, bv2, bv3;
                ldsm4(bv0, bv1, bv2, bv3, Bs_b + bab[p] + cb);
#pragma unroll
                for (int mt = 0; mt < 4; mt++) {
                    mma8(acc[mt][2 * p],     a[mt][0], a[mt][1], a[mt][2], a[mt][3], bv0, bv1);
                    mma8(acc[mt][2 * p + 1], a[mt][0], a[mt][1], a[mt][2], a[mt][3], bv2, bv3);
                }
            }
        }
    }

    // Epilogue
#pragma unroll
    for (int mt = 0; mt < 4; mt++) {
#pragma unroll
        for (int h = 0; h < 2; h++) {
            int m = m0 + wm0 + mt * 16 + (lane >> 2) + h * 8;
#pragma unroll
            for (int nt = 0; nt < 8; nt++) {
                int n = n0 + wn0 + nt * 8 + 2 * (lane & 3);
                float2 r;
                r.x = acc[mt][nt][h * 2 + 0] + bias[n];
                r.y = acc[mt][nt][h * 2 + 1] + bias[n + 1];
                if (mode == 1) {
                    r.x = f2tff(r.x);
                    r.y = f2tff(r.y);
                    int which = n >> 10;
                    int hh = (n >> 6) & (HH - 1);
                    int d = n & (DD - 1);
                    int b = m >> 11;
                    int t = m & (TT - 1);
                    float* p = g_qkv + (size_t)which * BHTD
                             + ((((size_t)b * HH + hh) * TT + t) * DD + d);
                    *(float2*)p = r;
                } else {
                    *(float2*)(Cout + (size_t)m * N + n) = r;
                }
            }
        }
    }
}

// ===========================================================================
// Flash attention v4 (causal), unchanged from R11.
// ===========================================================================
#define ATPB 128
#define KSD 68
#define VSD 72
#define KVSTG (64 * KSD + 64 * VSD)
#define PSM_FLOATS (4 * 32 * KSD)
#define SMEM_ATTN ((2 * KVSTG + PSM_FLOATS) * 4)
#define QSCALE (0.125f * 1.44269504088896f)

__global__ __launch_bounds__(ATPB, 2) void attn_tc()
{
    extern __shared__ float sm[];
    float* Psm = sm + 2 * KVSTG;

    int qb = gridDim.x - 1 - blockIdx.x;
    int bh = blockIdx.y;
    int q0 = qb * 128;
    int tid = threadIdx.x, lane = tid & 31, w = tid >> 5;
    int qw0 = q0 + w * 32;

    const float* qp = g_qkv + (size_t)bh * TT * DD;
    const float* kp = qp + (size_t)BHTD;
    const float* vp = qp + 2ull * BHTD;

    uint32_t smem_base = (uint32_t)__cvta_generic_to_shared(sm);

    int srow[8], sdq[8];
#pragma unroll
    for (int it = 0; it < 8; it++) {
        int l = tid + it * ATPB;
        srow[it] = l >> 4;
        sdq[it]  = (l & 15) * 4;
    }

    {
        uint32_t kb = smem_base;
        uint32_t vb = smem_base + 64 * KSD * 4;
#pragma unroll
        for (int it = 0; it < 8; it++) {
            int row = srow[it], dq = sdq[it];
            cp16ca(kb + (row * KSD + dq) * 4, kp + (size_t)row * DD + dq);
            cp16ca(vb + (row * VSD + dq) * 4, vp + (size_t)row * DD + dq);
        }
        cp_commit();
    }

    uint32_t krow[4];
#pragma unroll
    for (int p = 0; p < 4; p++) {
        int row = p * 16 + (lane & 7) + ((lane >> 4) << 3);
        krow[p] = (uint32_t)(row * KSD) * 4u + (uint32_t)(((lane >> 3) & 1) << 4);
    }

    uint32_t qa[2][8][4];
#pragma unroll
    for (int g = 0; g < 2; g++) {
        int r = qw0 + g * 16 + (lane >> 2);
#pragma unroll
        for (int c = 0; c < 8; c++) {
            int col = c * 8 + (lane & 3);
            qa[g][c][0] = f2tf(qp[(size_t)r * DD + col] * QSCALE);
            qa[g][c][1] = f2tf(qp[(size_t)(r + 8) * DD + col] * QSCALE);
            qa[g][c][2] = f2tf(qp[(size_t)r * DD + col + 4] * QSCALE);
            qa[g][c][3] = f2tf(qp[(size_t)(r + 8) * DD + col + 4] * QSCALE);
        }
    }

    float m_i[2][2], l_i[2][2];
    float oacc[2][8][4];
#pragma unroll
    for (int g = 0; g < 2; g++) {
        m_i[g][0] = m_i[g][1] = -1e30f;
        l_i[g][0] = l_i[g][1] = 0.f;
#pragma unroll
        for (int nt = 0; nt < 8; nt++)
#pragma unroll
            for (int j = 0; j < 4; j++) oacc[g][nt][j] = 0.f;
    }

    int jbmax = 2 * qb + 1;
    for (int jb = 0; jb <= jbmax; jb++) {
        int k0 = jb * 64;
        cp_wait<0>();
        __syncthreads();

        if (jb < jbmax) {
            int k1 = k0 + 64;
            uint32_t kb = smem_base + (size_t)((jb + 1) & 1) * KVSTG * 4;
            uint32_t vb = kb + 64 * KSD * 4;
#pragma unroll
            for (int it = 0; it < 8; it++) {
                int row = srow[it], dq = sdq[it];
                cp16ca(kb + (row * KSD + dq) * 4, kp + (size_t)(k1 + row) * DD + dq);
                cp16ca(vb + (row * VSD + dq) * 4, vp + (size_t)(k1 + row) * DD + dq);
            }
            cp_commit();
        }

        uint32_t Kb = smem_base + (uint32_t)((jb & 1) * KVSTG * 4);
        const uint32_t* Vu = (const uint32_t*)(sm + (size_t)(jb & 1) * KVSTG + 64 * KSD);

        if (k0 <= qw0 + 31) {
            float sacc[2][8][4];
#pragma unroll
            for (int g = 0; g < 2; g++)
#pragma unroll
                for (int nt = 0; nt < 8; nt++)
#pragma unroll
                    for (int j = 0; j < 4; j++) sacc[g][nt][j] = 0.f;
#pragma unroll
            for (int kc = 0; kc < 8; kc++) {
#pragma unroll
                for (int p = 0; p < 4; p++) {
                    uint32_t b0, b1, b2, b3;
                    ldsm4(b0, b1, b2, b3, Kb + krow[p] + (uint32_t)(kc * 32));
                    mma8(sacc[0][2 * p],     qa[0][kc][0], qa[0][kc][1], qa[0][kc][2], qa[0][kc][3], b0, b1);
                    mma8(sacc[1][2 * p],     qa[1][kc][0], qa[1][kc][1], qa[1][kc][2], qa[1][kc][3], b0, b1);
                    mma8(sacc[0][2 * p + 1], qa[0][kc][0], qa[0][kc][1], qa[0][kc][2], qa[0][kc][3], b2, b3);
                    mma8(sacc[1][2 * p + 1], qa[1][kc][0], qa[1][kc][1], qa[1][kc][2], qa[1][kc][3], b2, b3);
                }
            }

            if (k0 + 63 > qw0) {
#pragma unroll
                for (int g = 0; g < 2; g++) {
                    int r0 = qw0 + g * 16 + (lane >> 2);
#pragma unroll
                    for (int nt = 0; nt < 8; nt++) {
                        int col = k0 + nt * 8 + 2 * (lane & 3);
                        if (col     > r0)     sacc[g][nt][0] = -1e30f;
                        if (col + 1 > r0)     sacc[g][nt][1] = -1e30f;
                        if (col     > r0 + 8) sacc[g][nt][2] = -1e30f;
                        if (col + 1 > r0 + 8) sacc[g][nt][3] = -1e30f;
                    }
                }
            }

#pragma unroll
            for (int g = 0; g < 2; g++) {
#pragma unroll
                for (int h = 0; h < 2; h++) {
                    float mx = -1e30f;
#pragma unroll
                    for (int nt = 0; nt < 8; nt++) {
                        mx = fmaxf(mx, sacc[g][nt][h * 2 + 0]);
                        mx = fmaxf(mx, sacc[g][nt][h * 2 + 1]);
                    }
                    mx = fmaxf(mx, __shfl_xor_sync(0xffffffffu, mx, 1));
                    mx = fmaxf(mx, __shfl_xor_sync(0xffffffffu, mx, 2));
                    float mnew = fmaxf(m_i[g][h], mx);
                    float alpha = ex2(m_i[g][h] - mnew);
                    float rs = 0.f;
#pragma unroll
                    for (int nt = 0; nt < 8; nt++) {
                        float p0 = ex2(sacc[g][nt][h * 2 + 0] - mnew);
                        float p1 = ex2(sacc[g][nt][h * 2 + 1] - mnew);
                        sacc[g][nt][h * 2 + 0] = p0;
                        sacc[g][nt][h * 2 + 1] = p1;
                        rs += p0 + p1;
                    }
                    rs += __shfl_xor_sync(0xffffffffu, rs, 1);
                    rs += __shfl_xor_sync(0xffffffffu, rs, 2);
                    l_i[g][h] = l_i[g][h] * alpha + rs;
                    m_i[g][h] = mnew;
#pragma unroll
                    for (int nt = 0; nt < 8; nt++) {
                        oacc[g][nt][h * 2 + 0] *= alpha;
                        oacc[g][nt][h * 2 + 1] *= alpha;
                    }
                }
            }

            float* Pw = Psm + w * 32 * KSD;
#pragma unroll
            for (int g = 0; g < 2; g++) {
#pragma unroll
                for (int nt = 0; nt < 8; nt++) {
                    int col = nt * 8 + 2 * (lane & 3);
                    float2 p0, p1;
                    p0.x = sacc[g][nt][0]; p0.y = sacc[g][nt][1];
                    p1.x = sacc[g][nt][2]; p1.y = sacc[g][nt][3];
                    *(float2*)&Pw[(g * 16 + (lane >> 2)) * KSD + col] = p0;
                    *(float2*)&Pw[(g * 16 + (lane >> 2) + 8) * KSD + col] = p1;
                }
            }
            __syncwarp();
            const uint32_t* Pwu = (const uint32_t*)Pw;
#pragma unroll
            for (int kc = 0; kc < 8; kc++) {
                uint32_t a[2][4];
#pragma unroll
                for (int g = 0; g < 2; g++) {
                    a[g][0] = Pwu[(g * 16 + (lane >> 2)) * KSD + kc * 8 + (lane & 3)];
                    a[g][1] = Pwu[(g * 16 + (lane >> 2) + 8) * KSD + kc * 8 + (lane & 3)];
                    a[g][2] = Pwu[(g * 16 + (lane >> 2)) * KSD + kc * 8 + 4 + (lane & 3)];
                    a[g][3] = Pwu[(g * 16 + (lane >> 2) + 8) * KSD + kc * 8 + 4 + (lane & 3)];
                }
#pragma unroll
                for (int nt = 0; nt < 8; nt++) {
                    uint32_t b0 = Vu[(kc * 8 + (lane & 3)) * VSD + nt * 8 + (lane >> 2)];
                    uint32_t b1 = Vu[(kc * 8 + 4 + (lane & 3)) * VSD + nt * 8 + (lane >> 2)];
                    mma8(oacc[0][nt], a[0][0], a[0][1], a[0][2], a[0][3], b0, b1);
                    mma8(oacc[1][nt], a[1][0], a[1][1], a[1][2], a[1][3], b0, b1);
                }
            }
        }
        __syncthreads();
    }

    int bb = bh >> 4, hh = bh & (HH - 1);
#pragma unroll
    for (int g = 0; g < 2; g++) {
#pragma unroll
        for (int h = 0; h < 2; h++) {
            int row = qw0 + g * 16 + (lane >> 2) + h * 8;
            float inv = 1.f / l_i[g][h];
#pragma unroll
            for (int nt = 0; nt < 8; nt++) {
                int col = hh * DD + nt * 8 + 2 * (lane & 3);
                float2 r;
                r.x = f2tff(oacc[g][nt][h * 2 + 0] * inv);
                r.y = f2tff(oacc[g][nt][h * 2 + 1] * inv);
                *(float2*)(g_att + ((size_t)bb * TT + row) * CC + col) = r;
            }
        }
    }
}

// ===========================================================================
// Launch
// ===========================================================================
extern "C" void kernel_launch(void* const* d_in, const int* in_sizes, int n_in,
                              void* d_out, int out_size)
{
    (void)in_sizes; (void)n_in; (void)out_size;
    const float* x      = (const float*)d_in[0];
    const float* qkv_w  = (const float*)d_in[1];
    const float* qkv_b  = (const float*)d_in[2];
    const float* proj_w = (const float*)d_in[3];
    const float* proj_b = (const float*)d_in[4];
    float* out = (float*)d_out;

    cudaFuncSetAttribute(gemm_tc,
                         cudaFuncAttributeMaxDynamicSharedMemorySize, SMEM_GEMM);
    cudaFuncSetAttribute(attn_tc,
                         cudaFuncAttributeMaxDynamicSharedMemorySize, SMEM_ATTN);

    // Device addresses of __device__ symbols (host-side shadows are NOT valid
    // device pointers — must query; this is not an allocation).
    float* wq; float* wp;
    cudaGetSymbolAddress((void**)&wq, g_wqkv);
    cudaGetSymbolAddress((void**)&wp, g_wproj);

    // 0) pre-round all operands to tf32 grid (single launch)
    cvt_all<<<2048, 256>>>((const float4*)x, (const float4*)qkv_w,
                           (const float4*)proj_w);

    // 1) QKV projection + bias -> scatter tf32 [3][B,H,T,D]
    gemm_tc<<<dim3(3 * CC / GBN, BB * TT / GBM), 256, SMEM_GEMM>>>(
        wq, qkv_b, nullptr, BB * TT, 3 * CC, CC, 1);

    // 2) Causal flash attention -> g_att [B,T,C]
    attn_tc<<<dim3(TT / 128, BB * HH), ATPB, SMEM_ATTN>>>();

    // 3) Output projection + bias -> d_out
    gemm_tc<<<dim3(CC / GBN, BB * TT / GBM), 256, SMEM_GEMM>>>(
        wp, proj_b, out, BB * TT, CC, CC, 2);
}